// round 10
// baseline (speedup 1.0000x reference)
#include <cuda_runtime.h>
#include <cuda_fp16.h>
#include <cstdint>
#include <cstddef>

// ---------------- problem constants ----------------
#define BATCH   16384
#define DMODEL  1024
#define PHYSD   11
#define NTOK    4
#define NHEAD   4
#define DHEAD   256
#define DN      4096
#define LN_EPS  1e-5f

// ---------------- device scratch (allocation-free rule) ----------------
__device__ __half g_h      [(size_t)BATCH * DN];
__device__ __half g_physkv [(size_t)BATCH * DN];
__device__ __half g_kvln   [(size_t)BATCH * DN];
__device__ __half g_qln    [(size_t)BATCH * DMODEL];
__device__ __half g_qproj  [(size_t)BATCH * DMODEL];
__device__ __half g_kv     [(size_t)BATCH * NTOK * 2048];   // [k(1024)|v(1024)] per token
__device__ __half g_ctx    [(size_t)BATCH * DMODEL];
__device__ float  g_fused  [(size_t)BATCH * DMODEL];
__device__ __half g_fusedln[(size_t)BATCH * DMODEL];
__device__ __half g_ffh    [(size_t)BATCH * 2048];
// transposed weights [N][K] fp16
__device__ __half g_wt_pw2 [(size_t)DN * DN];
__device__ __half g_wt_q   [(size_t)DMODEL * DMODEL];
__device__ __half g_wt_kv  [(size_t)2048 * DMODEL];
__device__ __half g_wt_o   [(size_t)DMODEL * DMODEL];
__device__ __half g_wt_f1  [(size_t)2048 * DMODEL];
__device__ __half g_wt_f2  [(size_t)DMODEL * 2048];
__device__ float  g_b_kv   [2048];

// ---------------- helpers ----------------
__device__ __forceinline__ float gelu_f(float x) {
    float x3 = x * x * x;
    float t  = tanhf(0.79788456080286535588f * (x + 0.044715f * x3));
    return 0.5f * x * (1.0f + t);
}
__device__ __forceinline__ void cpa16(uint32_t sdst, const void* gsrc) {
    asm volatile("cp.async.cg.shared.global [%0], [%1], 16;\n" :: "r"(sdst), "l"(gsrc));
}
__device__ __forceinline__ void ldsm4(uint32_t& r0, uint32_t& r1, uint32_t& r2, uint32_t& r3,
                                      uint32_t addr) {
    asm volatile("ldmatrix.sync.aligned.m8n8.x4.shared.b16 {%0,%1,%2,%3}, [%4];"
                 : "=r"(r0), "=r"(r1), "=r"(r2), "=r"(r3) : "r"(addr));
}
// fp16-accumulate mma, zero-initialized c
__device__ __forceinline__ void mma_h_zero(uint32_t& d0, uint32_t& d1,
                                           const uint32_t* a, const uint32_t* b) {
    asm volatile(
        "mma.sync.aligned.m16n8k16.row.col.f16.f16.f16.f16 "
        "{%0,%1}, {%2,%3,%4,%5}, {%6,%7}, {%8,%9};\n"
        : "=r"(d0), "=r"(d1)
        : "r"(a[0]), "r"(a[1]), "r"(a[2]), "r"(a[3]),
          "r"(b[0]), "r"(b[1]), "r"(0u), "r"(0u));
}
// fp16-accumulate mma, accumulate onto d
__device__ __forceinline__ void mma_h_acc(uint32_t& d0, uint32_t& d1,
                                          const uint32_t* a, const uint32_t* b) {
    asm volatile(
        "mma.sync.aligned.m16n8k16.row.col.f16.f16.f16.f16 "
        "{%0,%1}, {%2,%3,%4,%5}, {%6,%7}, {%0,%1};\n"
        : "+r"(d0), "+r"(d1)
        : "r"(a[0]), "r"(a[1]), "r"(a[2]), "r"(a[3]),
          "r"(b[0]), "r"(b[1]));
}

// ================= fp16 GEMM: out[M,N] = A[M,K] @ Wt[N,K]^T + bias =================
// BM=128 BN=256 BK=32, 256 threads = 8 warps (2M x 4N), warp tile 64x64.
// fp16-accum mma over one k-tile (K=32), promoted to fp32 every k-tile.
enum { EPI_F32 = 0, EPI_HALF = 1, EPI_FUSED = 2, EPI_GELU_H = 3, EPI_ADDOUT = 4 };

#define LDK        40                         // halves per smem row (pad)
#define A_BYTES    (128 * LDK * 2)            // 10240
#define B_BYTES    (256 * LDK * 2)            // 20480
#define STAGE_B    (A_BYTES + B_BYTES)        // 30720
#define NSTAGE     4
#define SMEM_TOT   (STAGE_B * NSTAGE)         // 122880

template <int EPI>
__global__ __launch_bounds__(256, 1)
void gemm_h(const __half* __restrict__ A, const __half* __restrict__ Wt,
            const float* __restrict__ bias, void* __restrict__ outp,
            const float* __restrict__ aux, const float* __restrict__ gatep,
            int N, int K)
{
    extern __shared__ char smem[];
    const uint32_t sb = (uint32_t)__cvta_generic_to_shared(smem);

    const int tid  = threadIdx.x;
    const int lane = tid & 31;
    const int wid  = tid >> 5;
    const int wm   = wid >> 2;          // 0..1
    const int wn   = wid & 3;           // 0..3
    const int g    = lane >> 2;         // 0..7
    const int c    = lane & 3;          // 0..3
    const int m0   = blockIdx.y * 128;
    const int n0   = blockIdx.x * 256;

    const int a_row  = wm * 64 + (lane & 15);                      // + mi*16
    const int a_koff = (lane >> 4) << 3;                           // 0 or 8
    const int b_row  = wn * 64 + ((lane >> 4) << 3) + (lane & 7);  // + nj*16
    const int b_koff = lane & 8;                                   // 0 or 8

    float acc[4][8][4];
#pragma unroll
    for (int mi = 0; mi < 4; mi++)
#pragma unroll
        for (int ni = 0; ni < 8; ni++)
#pragma unroll
            for (int e = 0; e < 4; e++) acc[mi][ni][e] = 0.f;

    const int nt = K >> 5;

    auto fill = [&](int s, int kt) {
        const uint32_t a0 = sb + (uint32_t)s * STAGE_B;
        const uint32_t b0 = a0 + A_BYTES;
        const __half* Ag = A  + (size_t)m0 * K + kt * 32;
        const __half* Bg = Wt + (size_t)n0 * K + kt * 32;
#pragma unroll
        for (int i = 0; i < 2; i++) {
            int idx = tid + 256 * i;
            int r = idx >> 2, c8 = idx & 3;
            cpa16(a0 + (uint32_t)(r * LDK + c8 * 8) * 2, Ag + (size_t)r * K + c8 * 8);
        }
#pragma unroll
        for (int i = 0; i < 4; i++) {
            int idx = tid + 256 * i;
            int r = idx >> 2, c8 = idx & 3;
            cpa16(b0 + (uint32_t)(r * LDK + c8 * 8) * 2, Bg + (size_t)r * K + c8 * 8);
        }
        asm volatile("cp.async.commit_group;" ::: "memory");
    };

    fill(0, 0); fill(1, 1); fill(2, 2);

    for (int kt = 0; kt < nt; kt++) {
        const int rem = nt - 1 - kt;
        if (rem >= 2)      asm volatile("cp.async.wait_group 2;" ::: "memory");
        else if (rem == 1) asm volatile("cp.async.wait_group 1;" ::: "memory");
        else               asm volatile("cp.async.wait_group 0;" ::: "memory");
        __syncthreads();

        if (kt + 3 < nt) fill((kt + 3) & 3, kt + 3);

        const int s = kt & 3;
        const uint32_t aBase = sb + (uint32_t)s * STAGE_B;
        const uint32_t bBase = aBase + A_BYTES;

        // A fragments for both k-steps of this tile
        uint32_t af0[4][4], af1[4][4];
#pragma unroll
        for (int mi = 0; mi < 4; mi++)
            ldsm4(af0[mi][0], af0[mi][1], af0[mi][2], af0[mi][3],
                  aBase + (uint32_t)((a_row + mi * 16) * LDK + a_koff) * 2);
#pragma unroll
        for (int mi = 0; mi < 4; mi++)
            ldsm4(af1[mi][0], af1[mi][1], af1[mi][2], af1[mi][3],
                  aBase + (uint32_t)((a_row + mi * 16) * LDK + 16 + a_koff) * 2);

        // process ni in two halves to bound register pressure
#pragma unroll
        for (int h2 = 0; h2 < 2; h2++) {
            uint32_t bf0[4][2], bf1[4][2];
#pragma unroll
            for (int j = 0; j < 2; j++) {
                const int nj = h2 * 2 + j;
                uint32_t r0, r1, r2, r3;
                ldsm4(r0, r1, r2, r3,
                      bBase + (uint32_t)((b_row + nj * 16) * LDK + b_koff) * 2);
                bf0[2 * j][0] = r0; bf0[2 * j][1] = r1;
                bf0[2 * j + 1][0] = r2; bf0[2 * j + 1][1] = r3;
            }
#pragma unroll
            for (int j = 0; j < 2; j++) {
                const int nj = h2 * 2 + j;
                uint32_t r0, r1, r2, r3;
                ldsm4(r0, r1, r2, r3,
                      bBase + (uint32_t)((b_row + nj * 16) * LDK + 16 + b_koff) * 2);
                bf1[2 * j][0] = r0; bf1[2 * j][1] = r1;
                bf1[2 * j + 1][0] = r2; bf1[2 * j + 1][1] = r3;
            }

            uint32_t hacc[4][4][2];
#pragma unroll
            for (int mi = 0; mi < 4; mi++)
#pragma unroll
                for (int nl = 0; nl < 4; nl++)
                    mma_h_zero(hacc[mi][nl][0], hacc[mi][nl][1], af0[mi], bf0[nl]);
#pragma unroll
            for (int mi = 0; mi < 4; mi++)
#pragma unroll
                for (int nl = 0; nl < 4; nl++)
                    mma_h_acc(hacc[mi][nl][0], hacc[mi][nl][1], af1[mi], bf1[nl]);

            // promote k-tile partial sums into fp32 accumulators
#pragma unroll
            for (int mi = 0; mi < 4; mi++)
#pragma unroll
                for (int nl = 0; nl < 4; nl++) {
                    float2 lo = __half22float2(*(__half2*)&hacc[mi][nl][0]);
                    float2 hi = __half22float2(*(__half2*)&hacc[mi][nl][1]);
                    float* a4 = acc[mi][h2 * 4 + nl];
                    a4[0] += lo.x; a4[1] += lo.y; a4[2] += hi.x; a4[3] += hi.y;
                }
        }
    }

    // ---------------- epilogue ----------------
    float sig = 1.f;
    if (EPI == EPI_FUSED) sig = 1.f / (1.f + expf(-gatep[0]));

#pragma unroll
    for (int mi = 0; mi < 4; mi++) {
#pragma unroll
        for (int ni = 0; ni < 8; ni++) {
            const int col = n0 + wn * 64 + ni * 8 + 2 * c;
            const float b0 = bias[col], b1 = bias[col + 1];
#pragma unroll
            for (int half_ = 0; half_ < 2; half_++) {
                const int row = m0 + wm * 64 + mi * 16 + g + half_ * 8;
                const size_t oi = (size_t)row * N + col;
                float v0 = acc[mi][ni][half_ * 2 + 0] + b0;
                float v1 = acc[mi][ni][half_ * 2 + 1] + b1;
                if (EPI == EPI_F32) {
                    *(float2*)((float*)outp + oi) = make_float2(v0, v1);
                } else if (EPI == EPI_HALF) {
                    *(__half2*)((__half*)outp + oi) = __floats2half2_rn(v0, v1);
                } else if (EPI == EPI_FUSED) {
                    float2 a2 = *(const float2*)(aux + oi);
                    *(float2*)((float*)outp + oi) =
                        make_float2(a2.x + sig * v0, a2.y + sig * v1);
                } else if (EPI == EPI_GELU_H) {
                    *(__half2*)((__half*)outp + oi) =
                        __floats2half2_rn(gelu_f(v0), gelu_f(v1));
                } else { // EPI_ADDOUT
                    float2 a2 = *(const float2*)(aux + oi);
                    *(float2*)((float*)outp + oi) = make_float2(a2.x + v0, a2.y + v1);
                }
            }
        }
    }
}

// ================= weight transpose 64x64: Wt[n][k] = (half)W[k][n] =================
__global__ __launch_bounds__(256)
void transpose_w(const float* __restrict__ in, __half* __restrict__ out,
                 int rows, int cols)
{
    __shared__ float t[64][65];
    const int bx = blockIdx.x * 64;   // input col tile
    const int by = blockIdx.y * 64;   // input row tile
#pragma unroll
    for (int i = threadIdx.x; i < 1024; i += 256) {
        int r = i >> 4, c4 = (i & 15) * 4;
        float4 v = *(const float4*)&in[(size_t)(by + r) * cols + bx + c4];
        t[r][c4] = v.x; t[r][c4 + 1] = v.y; t[r][c4 + 2] = v.z; t[r][c4 + 3] = v.w;
    }
    __syncthreads();
#pragma unroll
    for (int i = threadIdx.x; i < 1024; i += 256) {
        int cc = i >> 4, r4 = (i & 15) * 4;
        __half2 h0 = __floats2half2_rn(t[r4][cc],     t[r4 + 1][cc]);
        __half2 h1 = __floats2half2_rn(t[r4 + 2][cc], t[r4 + 3][cc]);
        uint2 pk = make_uint2(*(uint32_t*)&h0, *(uint32_t*)&h1);
        *(uint2*)&out[(size_t)(bx + cc) * rows + by + r4] = pk;
    }
}

// ================= bias concat =================
__global__ void concat_bias(const float* __restrict__ a, const float* __restrict__ b,
                            float* __restrict__ o)
{
    int i = blockIdx.x * blockDim.x + threadIdx.x;
    o[i] = (i < 1024) ? a[i] : b[i - 1024];
}

// ================= phys MLP stage 1 (32 rows per block, pw1 reused) =================
__global__ __launch_bounds__(256)
void phys_mlp1(const float* __restrict__ phys, const float* __restrict__ pw1,
               const float* __restrict__ pb1, __half* __restrict__ out)
{
    __shared__ float p[32][PHYSD + 1];
    const int b0 = blockIdx.x * 32;
    const int tid = threadIdx.x;
    for (int i = tid; i < 32 * PHYSD; i += 256) {
        int r = i / PHYSD, k = i % PHYSD;
        p[r][k] = phys[(size_t)(b0 + r) * PHYSD + k];
    }
    __syncthreads();

    for (int n = tid; n < DN; n += 256) {
        float w[PHYSD];
#pragma unroll
        for (int k = 0; k < PHYSD; k++) w[k] = pw1[(size_t)k * DN + n];
        const float bb = pb1[n];
#pragma unroll 4
        for (int r = 0; r < 32; r++) {
            float s = bb;
#pragma unroll
            for (int k = 0; k < PHYSD; k++) s = fmaf(p[r][k], w[k], s);
            out[(size_t)(b0 + r) * DN + n] = __float2half_rn(gelu_f(s));
        }
    }
}

// ================= LayerNorm (D=1024), templated input, fp16 out =================
template <typename IT>
__global__ __launch_bounds__(256)
void ln1024(const IT* __restrict__ x, const float* __restrict__ gg,
            const float* __restrict__ bb, __half* __restrict__ out)
{
    __shared__ float red1[8], red2[8];
    const int row = blockIdx.x;
    const int tid = threadIdx.x;
    const int lane = tid & 31, wid = tid >> 5;

    float4 v;
    if (sizeof(IT) == 4) {
        v = *(const float4*)((const float*)x + (size_t)row * DMODEL + tid * 4);
    } else {
        uint2 pk = *(const uint2*)((const __half*)x + (size_t)row * DMODEL + tid * 4);
        float2 f0 = __half22float2(*(__half2*)&pk.x);
        float2 f1 = __half22float2(*(__half2*)&pk.y);
        v = make_float4(f0.x, f0.y, f1.x, f1.y);
    }
    float s1 = v.x + v.y + v.z + v.w;
    float s2 = v.x * v.x + v.y * v.y + v.z * v.z + v.w * v.w;
#pragma unroll
    for (int o = 16; o > 0; o >>= 1) {
        s1 += __shfl_down_sync(0xFFFFFFFFu, s1, o);
        s2 += __shfl_down_sync(0xFFFFFFFFu, s2, o);
    }
    if (lane == 0) { red1[wid] = s1; red2[wid] = s2; }
    __syncthreads();
    if (tid == 0) {
        float a = 0.f, b2 = 0.f;
#pragma unroll
        for (int i = 0; i < 8; i++) { a += red1[i]; b2 += red2[i]; }
        red1[0] = a; red2[0] = b2;
    }
    __syncthreads();
    const float mu  = red1[0] * (1.f / DMODEL);
    const float var = red2[0] * (1.f / DMODEL) - mu * mu;
    const float rs  = rsqrtf(var + LN_EPS);

    float4 gv = *(const float4*)(gg + tid * 4);
    float4 bv = *(const float4*)(bb + tid * 4);
    __half2 o0 = __floats2half2_rn((v.x - mu) * rs * gv.x + bv.x,
                                   (v.y - mu) * rs * gv.y + bv.y);
    __half2 o1 = __floats2half2_rn((v.z - mu) * rs * gv.z + bv.z,
                                   (v.w - mu) * rs * gv.w + bv.w);
    uint2 pk = make_uint2(*(uint32_t*)&o0, *(uint32_t*)&o1);
    *(uint2*)(out + (size_t)row * DMODEL + tid * 4) = pk;
}

// ================= attention: warp per (b, head), packed kv =================
__device__ __forceinline__ float dot8h(uint4 a, uint4 b) {
    const __half2* pa = (const __half2*)&a;
    const __half2* pb = (const __half2*)&b;
    float s = 0.f;
#pragma unroll
    for (int i = 0; i < 4; i++) {
        float2 fa = __half22float2(pa[i]);
        float2 fb = __half22float2(pb[i]);
        s = fmaf(fa.x, fb.x, s);
        s = fmaf(fa.y, fb.y, s);
    }
    return s;
}

__global__ __launch_bounds__(256)
void attn_kernel(const __half* __restrict__ q, const __half* __restrict__ kv,
                 __half* __restrict__ ctx)
{
    int warp = (blockIdx.x * 256 + threadIdx.x) >> 5;
    int lane = threadIdx.x & 31;
    int b = warp >> 2, h = warp & 3;

    size_t qoff = (size_t)b * DMODEL + h * DHEAD;
    uint4 qv = *(const uint4*)(q + qoff + lane * 8);

    float s[NTOK];
#pragma unroll
    for (int t = 0; t < NTOK; t++) {
        size_t koff = (size_t)(b * NTOK + t) * 2048 + h * DHEAD;
        uint4 kvec = *(const uint4*)(kv + koff + lane * 8);
        float d = dot8h(qv, kvec);
#pragma unroll
        for (int o = 16; o > 0; o >>= 1) d += __shfl_xor_sync(0xFFFFFFFFu, d, o);
        s[t] = d * (1.f / 16.f);   // 1/sqrt(256)
    }
    float m = fmaxf(fmaxf(s[0], s[1]), fmaxf(s[2], s[3]));
    float e[NTOK], sum = 0.f;
#pragma unroll
    for (int t = 0; t < NTOK; t++) { e[t] = expf(s[t] - m); sum += e[t]; }
    float inv = 1.f / sum;

    float cacc[8];
#pragma unroll
    for (int i = 0; i < 8; i++) cacc[i] = 0.f;
#pragma unroll
    for (int t = 0; t < NTOK; t++) {
        float a = e[t] * inv;
        size_t voff = (size_t)(b * NTOK + t) * 2048 + 1024 + h * DHEAD;
        uint4 vv = *(const uint4*)(kv + voff + lane * 8);
        const __half2* pv = (const __half2*)&vv;
#pragma unroll
        for (int i = 0; i < 4; i++) {
            float2 f = __half22float2(pv[i]);
            cacc[2 * i]     = fmaf(a, f.x, cacc[2 * i]);
            cacc[2 * i + 1] = fmaf(a, f.y, cacc[2 * i + 1]);
        }
    }
    uint4 ov;
    __half2* po = (__half2*)&ov;
#pragma unroll
    for (int i = 0; i < 4; i++)
        po[i] = __floats2half2_rn(cacc[2 * i], cacc[2 * i + 1]);
    *(uint4*)(ctx + qoff + lane * 8) = ov;
}

// ================= host launcher =================
extern "C" void kernel_launch(void* const* d_in, const int* in_sizes, int n_in,
                              void* d_out, int out_size)
{
    const float* embedding = (const float*)d_in[0];
    const float* physics   = (const float*)d_in[1];
    const float* pw1   = (const float*)d_in[2];
    const float* pb1   = (const float*)d_in[3];
    const float* pw2   = (const float*)d_in[4];
    const float* pb2   = (const float*)d_in[5];
    const float* lnq_g = (const float*)d_in[6];
    const float* lnq_b = (const float*)d_in[7];
    const float* lnkv_g = (const float*)d_in[8];
    const float* lnkv_b = (const float*)d_in[9];
    const float* wq = (const float*)d_in[10];
    const float* bq = (const float*)d_in[11];
    const float* wk = (const float*)d_in[12];
    const float* bk = (const float*)d_in[13];
    const float* wv = (const float*)d_in[14];
    const float* bv = (const float*)d_in[15];
    const float* wo = (const float*)d_in[16];
    const float* bo = (const float*)d_in[17];
    const float* ffn_g = (const float*)d_in[18];
    const float* ffn_b = (const float*)d_in[19];
    const float* fw1 = (const float*)d_in[20];
    const float* fb1 = (const float*)d_in[21];
    const float* fw2 = (const float*)d_in[22];
    const float* fb2 = (const float*)d_in[23];
    const float* gate = (const float*)d_in[24];
    float* out = (float*)d_out;

    __half *p_h, *p_physkv, *p_kvln, *p_qln, *p_qproj, *p_kv, *p_ctx, *p_fusedln, *p_ffh;
    __half *wt_pw2, *wt_q, *wt_kv, *wt_o, *wt_f1, *wt_f2;
    float  *p_fused, *p_bkv;
    cudaGetSymbolAddress((void**)&p_h, g_h);
    cudaGetSymbolAddress((void**)&p_physkv, g_physkv);
    cudaGetSymbolAddress((void**)&p_kvln, g_kvln);
    cudaGetSymbolAddress((void**)&p_qln, g_qln);
    cudaGetSymbolAddress((void**)&p_qproj, g_qproj);
    cudaGetSymbolAddress((void**)&p_kv, g_kv);
    cudaGetSymbolAddress((void**)&p_ctx, g_ctx);
    cudaGetSymbolAddress((void**)&p_fused, g_fused);
    cudaGetSymbolAddress((void**)&p_fusedln, g_fusedln);
    cudaGetSymbolAddress((void**)&p_ffh, g_ffh);
    cudaGetSymbolAddress((void**)&wt_pw2, g_wt_pw2);
    cudaGetSymbolAddress((void**)&wt_q, g_wt_q);
    cudaGetSymbolAddress((void**)&wt_kv, g_wt_kv);
    cudaGetSymbolAddress((void**)&wt_o, g_wt_o);
    cudaGetSymbolAddress((void**)&wt_f1, g_wt_f1);
    cudaGetSymbolAddress((void**)&wt_f2, g_wt_f2);
    cudaGetSymbolAddress((void**)&p_bkv, g_b_kv);

    cudaFuncSetAttribute(gemm_h<EPI_F32>,    cudaFuncAttributeMaxDynamicSharedMemorySize, SMEM_TOT);
    cudaFuncSetAttribute(gemm_h<EPI_HALF>,   cudaFuncAttributeMaxDynamicSharedMemorySize, SMEM_TOT);
    cudaFuncSetAttribute(gemm_h<EPI_FUSED>,  cudaFuncAttributeMaxDynamicSharedMemorySize, SMEM_TOT);
    cudaFuncSetAttribute(gemm_h<EPI_GELU_H>, cudaFuncAttributeMaxDynamicSharedMemorySize, SMEM_TOT);
    cudaFuncSetAttribute(gemm_h<EPI_ADDOUT>, cudaFuncAttributeMaxDynamicSharedMemorySize, SMEM_TOT);

    // launches 1-5, big GEMM is launch #6 (ncu -s 5 -c 1 captures it)
    transpose_w<<<dim3(DN / 64, DN / 64), 256>>>(pw2, wt_pw2, DN, DN);               // 1
    phys_mlp1<<<BATCH / 32, 256>>>(physics, pw1, pb1, p_h);                          // 2
    transpose_w<<<dim3(DMODEL / 64, DMODEL / 64), 256>>>(wk, wt_kv, DMODEL, DMODEL); // 3
    transpose_w<<<dim3(DMODEL / 64, DMODEL / 64), 256>>>(
        wv, wt_kv + (size_t)DMODEL * DMODEL, DMODEL, DMODEL);                        // 4
    transpose_w<<<dim3(DMODEL / 64, DMODEL / 64), 256>>>(wq, wt_q, DMODEL, DMODEL);  // 5

    // 6) BIG GEMM: physkv = h @ pw2 + pb2 (fp16 out)  [PROFILED]
    gemm_h<EPI_HALF><<<dim3(DN / 256, BATCH / 128), 256, SMEM_TOT>>>(
        p_h, wt_pw2, pb2, p_physkv, nullptr, nullptr, DN, DN);

    // remaining weight prep
    transpose_w<<<dim3(DMODEL / 64, DMODEL / 64), 256>>>(wo, wt_o, DMODEL, DMODEL);
    transpose_w<<<dim3(2048 / 64, DMODEL / 64), 256>>>(fw1, wt_f1, DMODEL, 2048);
    transpose_w<<<dim3(DMODEL / 64, 2048 / 64), 256>>>(fw2, wt_f2, 2048, DMODEL);
    concat_bias<<<2, 1024>>>(bk, bv, p_bkv);

    // LayerNorms -> fp16
    ln1024<__half><<<BATCH * NTOK, 256>>>(p_physkv, lnkv_g, lnkv_b, p_kvln);
    ln1024<float><<<BATCH, 256>>>(embedding, lnq_g, lnq_b, p_qln);

    // projections
    gemm_h<EPI_HALF><<<dim3(DMODEL / 256, BATCH / 128), 256, SMEM_TOT>>>(
        p_qln, wt_q, bq, p_qproj, nullptr, nullptr, DMODEL, DMODEL);
    gemm_h<EPI_HALF><<<dim3(2048 / 256, (BATCH * NTOK) / 128), 256, SMEM_TOT>>>(
        p_kvln, wt_kv, p_bkv, p_kv, nullptr, nullptr, 2048, DMODEL);

    // attention
    attn_kernel<<<(BATCH * NHEAD) / 8, 256>>>(p_qproj, p_kv, p_ctx);

    // fused = embedding + sigmoid(gate) * (ctx @ wo + bo)  (fp32)
    gemm_h<EPI_FUSED><<<dim3(DMODEL / 256, BATCH / 128), 256, SMEM_TOT>>>(
        p_ctx, wt_o, bo, p_fused, embedding, gate, DMODEL, DMODEL);

    // LN(fused) -> fp16
    ln1024<float><<<BATCH, 256>>>(p_fused, ffn_g, ffn_b, p_fusedln);

    // ffh = gelu(fusedln @ fw1 + fb1) -> fp16
    gemm_h<EPI_GELU_H><<<dim3(2048 / 256, BATCH / 128), 256, SMEM_TOT>>>(
        p_fusedln, wt_f1, fb1, p_ffh, nullptr, nullptr, 2048, DMODEL);

    // out = fused + ffh @ fw2 + fb2  (fp32)
    gemm_h<EPI_ADDOUT><<<dim3(DMODEL / 256, BATCH / 128), 256, SMEM_TOT>>>(
        p_ffh, wt_f2, fb2, out, p_fused, nullptr, DMODEL, 2048);
}

// round 11
// speedup vs baseline: 1.0405x; 1.0405x over previous
#include <cuda_runtime.h>
#include <cuda_fp16.h>
#include <cstdint>
#include <cstddef>

// ---------------- problem constants ----------------
#define BATCH   16384
#define DMODEL  1024
#define PHYSD   11
#define NTOK    4
#define NHEAD   4
#define DHEAD   256
#define DN      4096
#define LN_EPS  1e-5f

// ---------------- device scratch (allocation-free rule) ----------------
__device__ __half g_h      [(size_t)BATCH * DN];
__device__ __half g_physkv [(size_t)BATCH * DN];
__device__ __half g_kvln   [(size_t)BATCH * DN];
__device__ __half g_qln    [(size_t)BATCH * DMODEL];
__device__ __half g_qproj  [(size_t)BATCH * DMODEL];
__device__ __half g_kv     [(size_t)BATCH * NTOK * 2048];   // [k(1024)|v(1024)] per token
__device__ __half g_ctx    [(size_t)BATCH * DMODEL];
__device__ float  g_fused  [(size_t)BATCH * DMODEL];
__device__ __half g_fusedln[(size_t)BATCH * DMODEL];
__device__ __half g_ffh    [(size_t)BATCH * 2048];
// transposed weights [N][K] fp16
__device__ __half g_wt_pw2 [(size_t)DN * DN];
__device__ __half g_wt_q   [(size_t)DMODEL * DMODEL];
__device__ __half g_wt_kv  [(size_t)2048 * DMODEL];
__device__ __half g_wt_o   [(size_t)DMODEL * DMODEL];
__device__ __half g_wt_f1  [(size_t)2048 * DMODEL];
__device__ __half g_wt_f2  [(size_t)DMODEL * 2048];
__device__ float  g_b_kv   [2048];

// ---------------- helpers ----------------
__device__ __forceinline__ float gelu_f(float x) {
    float x3 = x * x * x;
    float t  = tanhf(0.79788456080286535588f * (x + 0.044715f * x3));
    return 0.5f * x * (1.0f + t);
}
__device__ __forceinline__ void cpa16(uint32_t sdst, const void* gsrc) {
    asm volatile("cp.async.cg.shared.global [%0], [%1], 16;\n" :: "r"(sdst), "l"(gsrc));
}
__device__ __forceinline__ void ldsm4(uint32_t& r0, uint32_t& r1, uint32_t& r2, uint32_t& r3,
                                      uint32_t addr) {
    asm volatile("ldmatrix.sync.aligned.m8n8.x4.shared.b16 {%0,%1,%2,%3}, [%4];"
                 : "=r"(r0), "=r"(r1), "=r"(r2), "=r"(r3) : "r"(addr));
}

// ================= persistent fp16 GEMM: out[M,N] = A[M,K] @ Wt[N,K]^T + bias ====
// BM=128 BN=256 BK=32, 256 threads = 8 warps (2M x 4N), warp tile 64x64.
// fp32-accum m16n8k16, ldmatrix, 4-stage cp.async ring flattened ACROSS tiles:
// each CTA walks tiles cta, cta+G, ... — next tile's fills overlap this tile's
// epilogue, removing per-tile prologue gaps and wave resync.
enum { EPI_F32 = 0, EPI_HALF = 1, EPI_FUSED = 2, EPI_GELU_H = 3, EPI_ADDOUT = 4 };

#define LDK        40                         // halves per smem row (pad)
#define A_BYTES    (128 * LDK * 2)            // 10240
#define B_BYTES    (256 * LDK * 2)            // 20480
#define STAGE_B    (A_BYTES + B_BYTES)        // 30720
#define NSTAGE     4
#define SMEM_TOT   (STAGE_B * NSTAGE)         // 122880

template <int EPI>
__global__ __launch_bounds__(256, 1)
void gemm_h(const __half* __restrict__ A, const __half* __restrict__ Wt,
            const float* __restrict__ bias, void* __restrict__ outp,
            const float* __restrict__ aux, const float* __restrict__ gatep,
            int N, int K, int nbx, int num_tiles)
{
    extern __shared__ char smem[];
    const uint32_t sb = (uint32_t)__cvta_generic_to_shared(smem);

    const int tid  = threadIdx.x;
    const int lane = tid & 31;
    const int wid  = tid >> 5;
    const int wm   = wid >> 2;          // 0..1
    const int wn   = wid & 3;           // 0..3
    const int g    = lane >> 2;         // 0..7
    const int c    = lane & 3;          // 0..3
    const int cta  = blockIdx.x;
    const int G    = gridDim.x;

    if (cta >= num_tiles) return;
    const int nt       = K >> 5;
    const int my_tiles = (num_tiles - 1 - cta) / G + 1;
    const int total    = my_tiles * nt;

    const int a_row  = wm * 64 + (lane & 15);                      // + mi*16
    const int a_koff = (lane >> 4) << 3;                           // 0 or 8
    const int b_row  = wn * 64 + ((lane >> 4) << 3) + (lane & 7);  // + nj*16
    const int b_koff = lane & 8;                                   // 0 or 8

    float acc[4][8][4];
#pragma unroll
    for (int mi = 0; mi < 4; mi++)
#pragma unroll
        for (int ni = 0; ni < 8; ni++)
#pragma unroll
            for (int e = 0; e < 4; e++) acc[mi][ni][e] = 0.f;

    // fill for flattened iteration j (tile-local index L = j/nt, k-tile = j%nt)
    auto fill = [&](int s, int j) {
        const int L  = j / nt;
        const int kt = j - L * nt;
        const int tile_id = cta + L * G;
        const int m0 = (tile_id / nbx) * 128;
        const int n0 = (tile_id % nbx) * 256;
        const uint32_t a0 = sb + (uint32_t)s * STAGE_B;
        const uint32_t b0 = a0 + A_BYTES;
        const __half* Ag = A  + (size_t)m0 * K + kt * 32;
        const __half* Bg = Wt + (size_t)n0 * K + kt * 32;
#pragma unroll
        for (int i = 0; i < 2; i++) {
            int idx = tid + 256 * i;
            int r = idx >> 2, c8 = idx & 3;
            cpa16(a0 + (uint32_t)(r * LDK + c8 * 8) * 2, Ag + (size_t)r * K + c8 * 8);
        }
#pragma unroll
        for (int i = 0; i < 4; i++) {
            int idx = tid + 256 * i;
            int r = idx >> 2, c8 = idx & 3;
            cpa16(b0 + (uint32_t)(r * LDK + c8 * 8) * 2, Bg + (size_t)r * K + c8 * 8);
        }
        asm volatile("cp.async.commit_group;" ::: "memory");
    };

    float sig = 1.f;
    if (EPI == EPI_FUSED) sig = 1.f / (1.f + expf(-gatep[0]));

    // prologue (total >= nt >= 32, so all three are valid)
    fill(0, 0); fill(1, 1); fill(2, 2);

    for (int j = 0; j < total; j++) {
        const int rem = total - 1 - j;
        if (rem >= 2)      asm volatile("cp.async.wait_group 2;" ::: "memory");
        else if (rem == 1) asm volatile("cp.async.wait_group 1;" ::: "memory");
        else               asm volatile("cp.async.wait_group 0;" ::: "memory");
        __syncthreads();

        if (j + 3 < total) fill((j + 3) & 3, j + 3);

        const int s = j & 3;
        const uint32_t aBase = sb + (uint32_t)s * STAGE_B;
        const uint32_t bBase = aBase + A_BYTES;

#pragma unroll
        for (int ks = 0; ks < 2; ks++) {
            const int k0 = ks * 16;
            uint32_t af[4][4];
#pragma unroll
            for (int mi = 0; mi < 4; mi++)
                ldsm4(af[mi][0], af[mi][1], af[mi][2], af[mi][3],
                      aBase + (uint32_t)((a_row + mi * 16) * LDK + k0 + a_koff) * 2);
            uint32_t bf[8][2];
#pragma unroll
            for (int nj = 0; nj < 4; nj++) {
                uint32_t r0, r1, r2, r3;
                ldsm4(r0, r1, r2, r3,
                      bBase + (uint32_t)((b_row + nj * 16) * LDK + k0 + b_koff) * 2);
                bf[2 * nj][0] = r0; bf[2 * nj][1] = r1;
                bf[2 * nj + 1][0] = r2; bf[2 * nj + 1][1] = r3;
            }
#pragma unroll
            for (int mi = 0; mi < 4; mi++)
#pragma unroll
                for (int ni = 0; ni < 8; ni++) {
                    asm volatile(
                        "mma.sync.aligned.m16n8k16.row.col.f32.f16.f16.f32 "
                        "{%0,%1,%2,%3}, {%4,%5,%6,%7}, {%8,%9}, {%0,%1,%2,%3};\n"
                        : "+f"(acc[mi][ni][0]), "+f"(acc[mi][ni][1]),
                          "+f"(acc[mi][ni][2]), "+f"(acc[mi][ni][3])
                        : "r"(af[mi][0]), "r"(af[mi][1]), "r"(af[mi][2]), "r"(af[mi][3]),
                          "r"(bf[ni][0]), "r"(bf[ni][1]));
                }
        }

        // ---------------- tile boundary: epilogue + reset ----------------
        if ((j + 1) % nt == 0) {
            const int tile_id = cta + (j / nt) * G;
            const int m0 = (tile_id / nbx) * 128;
            const int n0 = (tile_id % nbx) * 256;
#pragma unroll
            for (int mi = 0; mi < 4; mi++) {
#pragma unroll
                for (int ni = 0; ni < 8; ni++) {
                    const int col = n0 + wn * 64 + ni * 8 + 2 * c;
                    const float b0 = bias[col], b1 = bias[col + 1];
#pragma unroll
                    for (int half_ = 0; half_ < 2; half_++) {
                        const int row = m0 + wm * 64 + mi * 16 + g + half_ * 8;
                        const size_t oi = (size_t)row * N + col;
                        float v0 = acc[mi][ni][half_ * 2 + 0] + b0;
                        float v1 = acc[mi][ni][half_ * 2 + 1] + b1;
                        if (EPI == EPI_F32) {
                            *(float2*)((float*)outp + oi) = make_float2(v0, v1);
                        } else if (EPI == EPI_HALF) {
                            *(__half2*)((__half*)outp + oi) = __floats2half2_rn(v0, v1);
                        } else if (EPI == EPI_FUSED) {
                            float2 a2 = *(const float2*)(aux + oi);
                            *(float2*)((float*)outp + oi) =
                                make_float2(a2.x + sig * v0, a2.y + sig * v1);
                        } else if (EPI == EPI_GELU_H) {
                            *(__half2*)((__half*)outp + oi) =
                                __floats2half2_rn(gelu_f(v0), gelu_f(v1));
                        } else { // EPI_ADDOUT
                            float2 a2 = *(const float2*)(aux + oi);
                            *(float2*)((float*)outp + oi) = make_float2(a2.x + v0, a2.y + v1);
                        }
                    }
                }
            }
#pragma unroll
            for (int mi = 0; mi < 4; mi++)
#pragma unroll
                for (int ni = 0; ni < 8; ni++)
#pragma unroll
                    for (int e = 0; e < 4; e++) acc[mi][ni][e] = 0.f;
        }
    }
}

// ================= weight transpose 64x64: Wt[n][k] = (half)W[k][n] =================
__global__ __launch_bounds__(256)
void transpose_w(const float* __restrict__ in, __half* __restrict__ out,
                 int rows, int cols)
{
    __shared__ float t[64][65];
    const int bx = blockIdx.x * 64;   // input col tile
    const int by = blockIdx.y * 64;   // input row tile
#pragma unroll
    for (int i = threadIdx.x; i < 1024; i += 256) {
        int r = i >> 4, c4 = (i & 15) * 4;
        float4 v = *(const float4*)&in[(size_t)(by + r) * cols + bx + c4];
        t[r][c4] = v.x; t[r][c4 + 1] = v.y; t[r][c4 + 2] = v.z; t[r][c4 + 3] = v.w;
    }
    __syncthreads();
#pragma unroll
    for (int i = threadIdx.x; i < 1024; i += 256) {
        int cc = i >> 4, r4 = (i & 15) * 4;
        __half2 h0 = __floats2half2_rn(t[r4][cc],     t[r4 + 1][cc]);
        __half2 h1 = __floats2half2_rn(t[r4 + 2][cc], t[r4 + 3][cc]);
        uint2 pk = make_uint2(*(uint32_t*)&h0, *(uint32_t*)&h1);
        *(uint2*)&out[(size_t)(bx + cc) * rows + by + r4] = pk;
    }
}

// ================= bias concat =================
__global__ void concat_bias(const float* __restrict__ a, const float* __restrict__ b,
                            float* __restrict__ o)
{
    int i = blockIdx.x * blockDim.x + threadIdx.x;
    o[i] = (i < 1024) ? a[i] : b[i - 1024];
}

// ================= phys MLP stage 1 (32 rows per block, pw1 reused) =================
__global__ __launch_bounds__(256)
void phys_mlp1(const float* __restrict__ phys, const float* __restrict__ pw1,
               const float* __restrict__ pb1, __half* __restrict__ out)
{
    __shared__ float p[32][PHYSD + 1];
    const int b0 = blockIdx.x * 32;
    const int tid = threadIdx.x;
    for (int i = tid; i < 32 * PHYSD; i += 256) {
        int r = i / PHYSD, k = i % PHYSD;
        p[r][k] = phys[(size_t)(b0 + r) * PHYSD + k];
    }
    __syncthreads();

    for (int n = tid; n < DN; n += 256) {
        float w[PHYSD];
#pragma unroll
        for (int k = 0; k < PHYSD; k++) w[k] = pw1[(size_t)k * DN + n];
        const float bb = pb1[n];
#pragma unroll 4
        for (int r = 0; r < 32; r++) {
            float s = bb;
#pragma unroll
            for (int k = 0; k < PHYSD; k++) s = fmaf(p[r][k], w[k], s);
            out[(size_t)(b0 + r) * DN + n] = __float2half_rn(gelu_f(s));
        }
    }
}

// ================= LayerNorm (D=1024), templated input, fp16 out =================
template <typename IT>
__global__ __launch_bounds__(256)
void ln1024(const IT* __restrict__ x, const float* __restrict__ gg,
            const float* __restrict__ bb, __half* __restrict__ out)
{
    __shared__ float red1[8], red2[8];
    const int row = blockIdx.x;
    const int tid = threadIdx.x;
    const int lane = tid & 31, wid = tid >> 5;

    float4 v;
    if (sizeof(IT) == 4) {
        v = *(const float4*)((const float*)x + (size_t)row * DMODEL + tid * 4);
    } else {
        uint2 pk = *(const uint2*)((const __half*)x + (size_t)row * DMODEL + tid * 4);
        float2 f0 = __half22float2(*(__half2*)&pk.x);
        float2 f1 = __half22float2(*(__half2*)&pk.y);
        v = make_float4(f0.x, f0.y, f1.x, f1.y);
    }
    float s1 = v.x + v.y + v.z + v.w;
    float s2 = v.x * v.x + v.y * v.y + v.z * v.z + v.w * v.w;
#pragma unroll
    for (int o = 16; o > 0; o >>= 1) {
        s1 += __shfl_down_sync(0xFFFFFFFFu, s1, o);
        s2 += __shfl_down_sync(0xFFFFFFFFu, s2, o);
    }
    if (lane == 0) { red1[wid] = s1; red2[wid] = s2; }
    __syncthreads();
    if (tid == 0) {
        float a = 0.f, b2 = 0.f;
#pragma unroll
        for (int i = 0; i < 8; i++) { a += red1[i]; b2 += red2[i]; }
        red1[0] = a; red2[0] = b2;
    }
    __syncthreads();
    const float mu  = red1[0] * (1.f / DMODEL);
    const float var = red2[0] * (1.f / DMODEL) - mu * mu;
    const float rs  = rsqrtf(var + LN_EPS);

    float4 gv = *(const float4*)(gg + tid * 4);
    float4 bv = *(const float4*)(bb + tid * 4);
    __half2 o0 = __floats2half2_rn((v.x - mu) * rs * gv.x + bv.x,
                                   (v.y - mu) * rs * gv.y + bv.y);
    __half2 o1 = __floats2half2_rn((v.z - mu) * rs * gv.z + bv.z,
                                   (v.w - mu) * rs * gv.w + bv.w);
    uint2 pk = make_uint2(*(uint32_t*)&o0, *(uint32_t*)&o1);
    *(uint2*)(out + (size_t)row * DMODEL + tid * 4) = pk;
}

// ================= attention: warp per (b, head), packed kv =================
__device__ __forceinline__ float dot8h(uint4 a, uint4 b) {
    const __half2* pa = (const __half2*)&a;
    const __half2* pb = (const __half2*)&b;
    float s = 0.f;
#pragma unroll
    for (int i = 0; i < 4; i++) {
        float2 fa = __half22float2(pa[i]);
        float2 fb = __half22float2(pb[i]);
        s = fmaf(fa.x, fb.x, s);
        s = fmaf(fa.y, fb.y, s);
    }
    return s;
}

__global__ __launch_bounds__(256)
void attn_kernel(const __half* __restrict__ q, const __half* __restrict__ kv,
                 __half* __restrict__ ctx)
{
    int warp = (blockIdx.x * 256 + threadIdx.x) >> 5;
    int lane = threadIdx.x & 31;
    int b = warp >> 2, h = warp & 3;

    size_t qoff = (size_t)b * DMODEL + h * DHEAD;
    uint4 qv = *(const uint4*)(q + qoff + lane * 8);

    float s[NTOK];
#pragma unroll
    for (int t = 0; t < NTOK; t++) {
        size_t koff = (size_t)(b * NTOK + t) * 2048 + h * DHEAD;
        uint4 kvec = *(const uint4*)(kv + koff + lane * 8);
        float d = dot8h(qv, kvec);
#pragma unroll
        for (int o = 16; o > 0; o >>= 1) d += __shfl_xor_sync(0xFFFFFFFFu, d, o);
        s[t] = d * (1.f / 16.f);   // 1/sqrt(256)
    }
    float m = fmaxf(fmaxf(s[0], s[1]), fmaxf(s[2], s[3]));
    float e[NTOK], sum = 0.f;
#pragma unroll
    for (int t = 0; t < NTOK; t++) { e[t] = expf(s[t] - m); sum += e[t]; }
    float inv = 1.f / sum;

    float cacc[8];
#pragma unroll
    for (int i = 0; i < 8; i++) cacc[i] = 0.f;
#pragma unroll
    for (int t = 0; t < NTOK; t++) {
        float a = e[t] * inv;
        size_t voff = (size_t)(b * NTOK + t) * 2048 + 1024 + h * DHEAD;
        uint4 vv = *(const uint4*)(kv + voff + lane * 8);
        const __half2* pv = (const __half2*)&vv;
#pragma unroll
        for (int i = 0; i < 4; i++) {
            float2 f = __half22float2(pv[i]);
            cacc[2 * i]     = fmaf(a, f.x, cacc[2 * i]);
            cacc[2 * i + 1] = fmaf(a, f.y, cacc[2 * i + 1]);
        }
    }
    uint4 ov;
    __half2* po = (__half2*)&ov;
#pragma unroll
    for (int i = 0; i < 4; i++)
        po[i] = __floats2half2_rn(cacc[2 * i], cacc[2 * i + 1]);
    *(uint4*)(ctx + qoff + lane * 8) = ov;
}

// ================= host launcher =================
extern "C" void kernel_launch(void* const* d_in, const int* in_sizes, int n_in,
                              void* d_out, int out_size)
{
    const float* embedding = (const float*)d_in[0];
    const float* physics   = (const float*)d_in[1];
    const float* pw1   = (const float*)d_in[2];
    const float* pb1   = (const float*)d_in[3];
    const float* pw2   = (const float*)d_in[4];
    const float* pb2   = (const float*)d_in[5];
    const float* lnq_g = (const float*)d_in[6];
    const float* lnq_b = (const float*)d_in[7];
    const float* lnkv_g = (const float*)d_in[8];
    const float* lnkv_b = (const float*)d_in[9];
    const float* wq = (const float*)d_in[10];
    const float* bq = (const float*)d_in[11];
    const float* wk = (const float*)d_in[12];
    const float* bk = (const float*)d_in[13];
    const float* wv = (const float*)d_in[14];
    const float* bv = (const float*)d_in[15];
    const float* wo = (const float*)d_in[16];
    const float* bo = (const float*)d_in[17];
    const float* ffn_g = (const float*)d_in[18];
    const float* ffn_b = (const float*)d_in[19];
    const float* fw1 = (const float*)d_in[20];
    const float* fb1 = (const float*)d_in[21];
    const float* fw2 = (const float*)d_in[22];
    const float* fb2 = (const float*)d_in[23];
    const float* gate = (const float*)d_in[24];
    float* out = (float*)d_out;

    __half *p_h, *p_physkv, *p_kvln, *p_qln, *p_qproj, *p_kv, *p_ctx, *p_fusedln, *p_ffh;
    __half *wt_pw2, *wt_q, *wt_kv, *wt_o, *wt_f1, *wt_f2;
    float  *p_fused, *p_bkv;
    cudaGetSymbolAddress((void**)&p_h, g_h);
    cudaGetSymbolAddress((void**)&p_physkv, g_physkv);
    cudaGetSymbolAddress((void**)&p_kvln, g_kvln);
    cudaGetSymbolAddress((void**)&p_qln, g_qln);
    cudaGetSymbolAddress((void**)&p_qproj, g_qproj);
    cudaGetSymbolAddress((void**)&p_kv, g_kv);
    cudaGetSymbolAddress((void**)&p_ctx, g_ctx);
    cudaGetSymbolAddress((void**)&p_fused, g_fused);
    cudaGetSymbolAddress((void**)&p_fusedln, g_fusedln);
    cudaGetSymbolAddress((void**)&p_ffh, g_ffh);
    cudaGetSymbolAddress((void**)&wt_pw2, g_wt_pw2);
    cudaGetSymbolAddress((void**)&wt_q, g_wt_q);
    cudaGetSymbolAddress((void**)&wt_kv, g_wt_kv);
    cudaGetSymbolAddress((void**)&wt_o, g_wt_o);
    cudaGetSymbolAddress((void**)&wt_f1, g_wt_f1);
    cudaGetSymbolAddress((void**)&wt_f2, g_wt_f2);
    cudaGetSymbolAddress((void**)&p_bkv, g_b_kv);

    cudaFuncSetAttribute(gemm_h<EPI_F32>,    cudaFuncAttributeMaxDynamicSharedMemorySize, SMEM_TOT);
    cudaFuncSetAttribute(gemm_h<EPI_HALF>,   cudaFuncAttributeMaxDynamicSharedMemorySize, SMEM_TOT);
    cudaFuncSetAttribute(gemm_h<EPI_FUSED>,  cudaFuncAttributeMaxDynamicSharedMemorySize, SMEM_TOT);
    cudaFuncSetAttribute(gemm_h<EPI_GELU_H>, cudaFuncAttributeMaxDynamicSharedMemorySize, SMEM_TOT);
    cudaFuncSetAttribute(gemm_h<EPI_ADDOUT>, cudaFuncAttributeMaxDynamicSharedMemorySize, SMEM_TOT);

    int nsm = 148;
    cudaDeviceGetAttribute(&nsm, cudaDevAttrMultiProcessorCount, 0);

    auto grid_for = [&](int tiles) { return dim3((unsigned)(tiles < nsm ? tiles : nsm)); };

    // tile counts (M/128 * N/256)
    const int T_BIG = (BATCH / 128) * (DN / 256);            // 2048, nbx=16
    const int T_Q   = (BATCH / 128) * (DMODEL / 256);        // 512,  nbx=4
    const int T_KV  = ((BATCH * NTOK) / 128) * (2048 / 256); // 4096, nbx=8
    const int T_D   = (BATCH / 128) * (DMODEL / 256);        // 512,  nbx=4
    const int T_F1  = (BATCH / 128) * (2048 / 256);          // 1024, nbx=8

    // weight prep + phys stage 1
    transpose_w<<<dim3(DN / 64, DN / 64), 256>>>(pw2, wt_pw2, DN, DN);
    phys_mlp1<<<BATCH / 32, 256>>>(physics, pw1, pb1, p_h);
    transpose_w<<<dim3(DMODEL / 64, DMODEL / 64), 256>>>(wk, wt_kv, DMODEL, DMODEL);
    transpose_w<<<dim3(DMODEL / 64, DMODEL / 64), 256>>>(
        wv, wt_kv + (size_t)DMODEL * DMODEL, DMODEL, DMODEL);
    transpose_w<<<dim3(DMODEL / 64, DMODEL / 64), 256>>>(wq, wt_q, DMODEL, DMODEL);

    // BIG GEMM: physkv = h @ pw2 + pb2 (fp16 out)
    gemm_h<EPI_HALF><<<grid_for(T_BIG), 256, SMEM_TOT>>>(
        p_h, wt_pw2, pb2, p_physkv, nullptr, nullptr, DN, DN, DN / 256, T_BIG);

    // remaining weight prep
    transpose_w<<<dim3(DMODEL / 64, DMODEL / 64), 256>>>(wo, wt_o, DMODEL, DMODEL);
    transpose_w<<<dim3(2048 / 64, DMODEL / 64), 256>>>(fw1, wt_f1, DMODEL, 2048);
    transpose_w<<<dim3(DMODEL / 64, 2048 / 64), 256>>>(fw2, wt_f2, 2048, DMODEL);
    concat_bias<<<2, 1024>>>(bk, bv, p_bkv);

    // LayerNorms -> fp16
    ln1024<__half><<<BATCH * NTOK, 256>>>(p_physkv, lnkv_g, lnkv_b, p_kvln);
    ln1024<float><<<BATCH, 256>>>(embedding, lnq_g, lnq_b, p_qln);

    // projections
    gemm_h<EPI_HALF><<<grid_for(T_Q), 256, SMEM_TOT>>>(
        p_qln, wt_q, bq, p_qproj, nullptr, nullptr, DMODEL, DMODEL, DMODEL / 256, T_Q);
    gemm_h<EPI_HALF><<<grid_for(T_KV), 256, SMEM_TOT>>>(
        p_kvln, wt_kv, p_bkv, p_kv, nullptr, nullptr, 2048, DMODEL, 2048 / 256, T_KV);

    // attention
    attn_kernel<<<(BATCH * NHEAD) / 8, 256>>>(p_qproj, p_kv, p_ctx);

    // fused = embedding + sigmoid(gate) * (ctx @ wo + bo)  (fp32)
    gemm_h<EPI_FUSED><<<grid_for(T_D), 256, SMEM_TOT>>>(
        p_ctx, wt_o, bo, p_fused, embedding, gate, DMODEL, DMODEL, DMODEL / 256, T_D);

    // LN(fused) -> fp16
    ln1024<float><<<BATCH, 256>>>(p_fused, ffn_g, ffn_b, p_fusedln);

    // ffh = gelu(fusedln @ fw1 + fb1) -> fp16
    gemm_h<EPI_GELU_H><<<grid_for(T_F1), 256, SMEM_TOT>>>(
        p_fusedln, wt_f1, fb1, p_ffh, nullptr, nullptr, 2048, DMODEL, 2048 / 256, T_F1);

    // out = fused + ffh @ fw2 + fb2  (fp32)
    gemm_h<EPI_ADDOUT><<<grid_for(T_D), 256, SMEM_TOT>>>(
        p_ffh, wt_f2, fb2, out, p_fused, nullptr, DMODEL, 2048, DMODEL / 256, T_D);
}

// round 12
// speedup vs baseline: 1.1897x; 1.1434x over previous
#include <cuda_runtime.h>
#include <cuda_fp16.h>
#include <cstdint>
#include <cstddef>

// ---------------- problem constants ----------------
#define BATCH   16384
#define DMODEL  1024
#define PHYSD   11
#define NTOK    4
#define NHEAD   4
#define DHEAD   256
#define DN      4096
#define LN_EPS  1e-5f

// ---------------- device scratch (allocation-free rule) ----------------
__device__ __half g_h      [(size_t)BATCH * DN];
__device__ __half g_physkv [(size_t)BATCH * DN];
__device__ __half g_kvln   [(size_t)BATCH * DN];
__device__ __half g_qln    [(size_t)BATCH * DMODEL];
__device__ __half g_qproj  [(size_t)BATCH * DMODEL];
__device__ __half g_kv     [(size_t)BATCH * NTOK * 2048];   // [k(1024)|v(1024)] per token
__device__ __half g_ctx    [(size_t)BATCH * DMODEL];
__device__ float  g_fused  [(size_t)BATCH * DMODEL];
__device__ __half g_fusedln[(size_t)BATCH * DMODEL];
__device__ __half g_ffh    [(size_t)BATCH * 2048];
// transposed weights [N][K] fp16
__device__ __half g_wt_pw2 [(size_t)DN * DN];
__device__ __half g_wt_q   [(size_t)DMODEL * DMODEL];
__device__ __half g_wt_kv  [(size_t)2048 * DMODEL];
__device__ __half g_wt_o   [(size_t)DMODEL * DMODEL];
__device__ __half g_wt_f1  [(size_t)2048 * DMODEL];
__device__ __half g_wt_f2  [(size_t)DMODEL * 2048];
__device__ float  g_b_kv   [2048];

// ---------------- helpers ----------------
__device__ __forceinline__ float gelu_f(float x) {
    float x3 = x * x * x;
    float t  = tanhf(0.79788456080286535588f * (x + 0.044715f * x3));
    return 0.5f * x * (1.0f + t);
}
__device__ __forceinline__ void cpa16(uint32_t sdst, const void* gsrc) {
    asm volatile("cp.async.cg.shared.global [%0], [%1], 16;\n" :: "r"(sdst), "l"(gsrc));
}
__device__ __forceinline__ void ldsm4(uint32_t& r0, uint32_t& r1, uint32_t& r2, uint32_t& r3,
                                      uint32_t addr) {
    asm volatile("ldmatrix.sync.aligned.m8n8.x4.shared.b16 {%0,%1,%2,%3}, [%4];"
                 : "=r"(r0), "=r"(r1), "=r"(r2), "=r"(r3) : "r"(addr));
}

// ================= fp16 GEMM: out[M,N] = A[M,K] @ Wt[N,K]^T + bias =================
// BM=128 BN=256 BK=32, 256 threads = 8 warps (2M x 4N), warp tile 64x64.
// fp32-accum m16n8k16, ldmatrix, 4-stage cp.async, 1 barrier/k-tile. (R8 config.)
enum { EPI_F32 = 0, EPI_HALF = 1, EPI_FUSED = 2, EPI_GELU_H = 3, EPI_ADDOUT = 4 };

#define LDK        40                         // halves per smem row (pad)
#define A_BYTES    (128 * LDK * 2)            // 10240
#define B_BYTES    (256 * LDK * 2)            // 20480
#define STAGE_B    (A_BYTES + B_BYTES)        // 30720
#define NSTAGE     4
#define SMEM_TOT   (STAGE_B * NSTAGE)         // 122880

template <int EPI>
__global__ __launch_bounds__(256, 1)
void gemm_h(const __half* __restrict__ A, const __half* __restrict__ Wt,
            const float* __restrict__ bias, void* __restrict__ outp,
            const float* __restrict__ aux, const float* __restrict__ gatep,
            int N, int K)
{
    extern __shared__ char smem[];
    const uint32_t sb = (uint32_t)__cvta_generic_to_shared(smem);

    const int tid  = threadIdx.x;
    const int lane = tid & 31;
    const int wid  = tid >> 5;
    const int wm   = wid >> 2;          // 0..1
    const int wn   = wid & 3;           // 0..3
    const int g    = lane >> 2;         // 0..7
    const int c    = lane & 3;          // 0..3
    const int m0   = blockIdx.y * 128;
    const int n0   = blockIdx.x * 256;

    const int a_row  = wm * 64 + (lane & 15);                      // + mi*16
    const int a_koff = (lane >> 4) << 3;                           // 0 or 8
    const int b_row  = wn * 64 + ((lane >> 4) << 3) + (lane & 7);  // + nj*16
    const int b_koff = lane & 8;                                   // 0 or 8

    float acc[4][8][4];
#pragma unroll
    for (int mi = 0; mi < 4; mi++)
#pragma unroll
        for (int ni = 0; ni < 8; ni++)
#pragma unroll
            for (int e = 0; e < 4; e++) acc[mi][ni][e] = 0.f;

    const int nt = K >> 5;

    auto fill = [&](int s, int kt) {
        const uint32_t a0 = sb + (uint32_t)s * STAGE_B;
        const uint32_t b0 = a0 + A_BYTES;
        const __half* Ag = A  + (size_t)m0 * K + kt * 32;
        const __half* Bg = Wt + (size_t)n0 * K + kt * 32;
#pragma unroll
        for (int i = 0; i < 2; i++) {
            int idx = tid + 256 * i;
            int r = idx >> 2, c8 = idx & 3;
            cpa16(a0 + (uint32_t)(r * LDK + c8 * 8) * 2, Ag + (size_t)r * K + c8 * 8);
        }
#pragma unroll
        for (int i = 0; i < 4; i++) {
            int idx = tid + 256 * i;
            int r = idx >> 2, c8 = idx & 3;
            cpa16(b0 + (uint32_t)(r * LDK + c8 * 8) * 2, Bg + (size_t)r * K + c8 * 8);
        }
        asm volatile("cp.async.commit_group;" ::: "memory");
    };

    fill(0, 0); fill(1, 1); fill(2, 2);

    for (int kt = 0; kt < nt; kt++) {
        const int rem = nt - 1 - kt;
        if (rem >= 2)      asm volatile("cp.async.wait_group 2;" ::: "memory");
        else if (rem == 1) asm volatile("cp.async.wait_group 1;" ::: "memory");
        else               asm volatile("cp.async.wait_group 0;" ::: "memory");
        __syncthreads();

        if (kt + 3 < nt) fill((kt + 3) & 3, kt + 3);

        const int s = kt & 3;
        const uint32_t aBase = sb + (uint32_t)s * STAGE_B;
        const uint32_t bBase = aBase + A_BYTES;

#pragma unroll
        for (int ks = 0; ks < 2; ks++) {
            const int k0 = ks * 16;
            uint32_t af[4][4];
#pragma unroll
            for (int mi = 0; mi < 4; mi++)
                ldsm4(af[mi][0], af[mi][1], af[mi][2], af[mi][3],
                      aBase + (uint32_t)((a_row + mi * 16) * LDK + k0 + a_koff) * 2);
            uint32_t bf[8][2];
#pragma unroll
            for (int nj = 0; nj < 4; nj++) {
                uint32_t r0, r1, r2, r3;
                ldsm4(r0, r1, r2, r3,
                      bBase + (uint32_t)((b_row + nj * 16) * LDK + k0 + b_koff) * 2);
                bf[2 * nj][0] = r0; bf[2 * nj][1] = r1;
                bf[2 * nj + 1][0] = r2; bf[2 * nj + 1][1] = r3;
            }
#pragma unroll
            for (int mi = 0; mi < 4; mi++)
#pragma unroll
                for (int ni = 0; ni < 8; ni++) {
                    asm volatile(
                        "mma.sync.aligned.m16n8k16.row.col.f32.f16.f16.f32 "
                        "{%0,%1,%2,%3}, {%4,%5,%6,%7}, {%8,%9}, {%0,%1,%2,%3};\n"
                        : "+f"(acc[mi][ni][0]), "+f"(acc[mi][ni][1]),
                          "+f"(acc[mi][ni][2]), "+f"(acc[mi][ni][3])
                        : "r"(af[mi][0]), "r"(af[mi][1]), "r"(af[mi][2]), "r"(af[mi][3]),
                          "r"(bf[ni][0]), "r"(bf[ni][1]));
                }
        }
    }

    // ---------------- epilogue ----------------
    float sig = 1.f;
    if (EPI == EPI_FUSED) sig = 1.f / (1.f + expf(-gatep[0]));

#pragma unroll
    for (int mi = 0; mi < 4; mi++) {
#pragma unroll
        for (int ni = 0; ni < 8; ni++) {
            const int col = n0 + wn * 64 + ni * 8 + 2 * c;
            const float b0 = bias[col], b1 = bias[col + 1];
#pragma unroll
            for (int half_ = 0; half_ < 2; half_++) {
                const int row = m0 + wm * 64 + mi * 16 + g + half_ * 8;
                const size_t oi = (size_t)row * N + col;
                float v0 = acc[mi][ni][half_ * 2 + 0] + b0;
                float v1 = acc[mi][ni][half_ * 2 + 1] + b1;
                if (EPI == EPI_F32) {
                    *(float2*)((float*)outp + oi) = make_float2(v0, v1);
                } else if (EPI == EPI_HALF) {
                    *(__half2*)((__half*)outp + oi) = __floats2half2_rn(v0, v1);
                } else if (EPI == EPI_FUSED) {
                    float2 a2 = *(const float2*)(aux + oi);
                    *(float2*)((float*)outp + oi) =
                        make_float2(a2.x + sig * v0, a2.y + sig * v1);
                } else if (EPI == EPI_GELU_H) {
                    *(__half2*)((__half*)outp + oi) =
                        __floats2half2_rn(gelu_f(v0), gelu_f(v1));
                } else { // EPI_ADDOUT
                    float2 a2 = *(const float2*)(aux + oi);
                    *(float2*)((float*)outp + oi) = make_float2(a2.x + v0, a2.y + v1);
                }
            }
        }
    }
}

// ================= weight transpose 64x64: Wt[n][k] = (half)W[k][n] =================
__global__ __launch_bounds__(256)
void transpose_w(const float* __restrict__ in, __half* __restrict__ out,
                 int rows, int cols)
{
    __shared__ float t[64][65];
    const int bx = blockIdx.x * 64;   // input col tile
    const int by = blockIdx.y * 64;   // input row tile
#pragma unroll
    for (int i = threadIdx.x; i < 1024; i += 256) {
        int r = i >> 4, c4 = (i & 15) * 4;
        float4 v = *(const float4*)&in[(size_t)(by + r) * cols + bx + c4];
        t[r][c4] = v.x; t[r][c4 + 1] = v.y; t[r][c4 + 2] = v.z; t[r][c4 + 3] = v.w;
    }
    __syncthreads();
#pragma unroll
    for (int i = threadIdx.x; i < 1024; i += 256) {
        int cc = i >> 4, r4 = (i & 15) * 4;
        __half2 h0 = __floats2half2_rn(t[r4][cc],     t[r4 + 1][cc]);
        __half2 h1 = __floats2half2_rn(t[r4 + 2][cc], t[r4 + 3][cc]);
        uint2 pk = make_uint2(*(uint32_t*)&h0, *(uint32_t*)&h1);
        *(uint2*)&out[(size_t)(bx + cc) * rows + by + r4] = pk;
    }
}

// ================= bias concat =================
__global__ void concat_bias(const float* __restrict__ a, const float* __restrict__ b,
                            float* __restrict__ o)
{
    int i = blockIdx.x * blockDim.x + threadIdx.x;
    o[i] = (i < 1024) ? a[i] : b[i - 1024];
}

// ================= phys MLP stage 1 (32 rows per block, pw1 reused) =================
__global__ __launch_bounds__(256)
void phys_mlp1(const float* __restrict__ phys, const float* __restrict__ pw1,
               const float* __restrict__ pb1, __half* __restrict__ out)
{
    __shared__ float p[32][PHYSD + 1];
    const int b0 = blockIdx.x * 32;
    const int tid = threadIdx.x;
    for (int i = tid; i < 32 * PHYSD; i += 256) {
        int r = i / PHYSD, k = i % PHYSD;
        p[r][k] = phys[(size_t)(b0 + r) * PHYSD + k];
    }
    __syncthreads();

    for (int n = tid; n < DN; n += 256) {
        float w[PHYSD];
#pragma unroll
        for (int k = 0; k < PHYSD; k++) w[k] = pw1[(size_t)k * DN + n];
        const float bb = pb1[n];
#pragma unroll 4
        for (int r = 0; r < 32; r++) {
            float s = bb;
#pragma unroll
            for (int k = 0; k < PHYSD; k++) s = fmaf(p[r][k], w[k], s);
            out[(size_t)(b0 + r) * DN + n] = __float2half_rn(gelu_f(s));
        }
    }
}

// ================= LayerNorm (D=1024), templated input, fp16 out =================
template <typename IT>
__global__ __launch_bounds__(256)
void ln1024(const IT* __restrict__ x, const float* __restrict__ gg,
            const float* __restrict__ bb, __half* __restrict__ out)
{
    __shared__ float red1[8], red2[8];
    const int row = blockIdx.x;
    const int tid = threadIdx.x;
    const int lane = tid & 31, wid = tid >> 5;

    float4 v;
    if (sizeof(IT) == 4) {
        v = *(const float4*)((const float*)x + (size_t)row * DMODEL + tid * 4);
    } else {
        uint2 pk = *(const uint2*)((const __half*)x + (size_t)row * DMODEL + tid * 4);
        float2 f0 = __half22float2(*(__half2*)&pk.x);
        float2 f1 = __half22float2(*(__half2*)&pk.y);
        v = make_float4(f0.x, f0.y, f1.x, f1.y);
    }
    float s1 = v.x + v.y + v.z + v.w;
    float s2 = v.x * v.x + v.y * v.y + v.z * v.z + v.w * v.w;
#pragma unroll
    for (int o = 16; o > 0; o >>= 1) {
        s1 += __shfl_down_sync(0xFFFFFFFFu, s1, o);
        s2 += __shfl_down_sync(0xFFFFFFFFu, s2, o);
    }
    if (lane == 0) { red1[wid] = s1; red2[wid] = s2; }
    __syncthreads();
    if (tid == 0) {
        float a = 0.f, b2 = 0.f;
#pragma unroll
        for (int i = 0; i < 8; i++) { a += red1[i]; b2 += red2[i]; }
        red1[0] = a; red2[0] = b2;
    }
    __syncthreads();
    const float mu  = red1[0] * (1.f / DMODEL);
    const float var = red2[0] * (1.f / DMODEL) - mu * mu;
    const float rs  = rsqrtf(var + LN_EPS);

    float4 gv = *(const float4*)(gg + tid * 4);
    float4 bv = *(const float4*)(bb + tid * 4);
    __half2 o0 = __floats2half2_rn((v.x - mu) * rs * gv.x + bv.x,
                                   (v.y - mu) * rs * gv.y + bv.y);
    __half2 o1 = __floats2half2_rn((v.z - mu) * rs * gv.z + bv.z,
                                   (v.w - mu) * rs * gv.w + bv.w);
    uint2 pk = make_uint2(*(uint32_t*)&o0, *(uint32_t*)&o1);
    *(uint2*)(out + (size_t)row * DMODEL + tid * 4) = pk;
}

// ================= attention: warp per (b, head), packed kv =================
__device__ __forceinline__ float dot8h(uint4 a, uint4 b) {
    const __half2* pa = (const __half2*)&a;
    const __half2* pb = (const __half2*)&b;
    float s = 0.f;
#pragma unroll
    for (int i = 0; i < 4; i++) {
        float2 fa = __half22float2(pa[i]);
        float2 fb = __half22float2(pb[i]);
        s = fmaf(fa.x, fb.x, s);
        s = fmaf(fa.y, fb.y, s);
    }
    return s;
}

__global__ __launch_bounds__(256)
void attn_kernel(const __half* __restrict__ q, const __half* __restrict__ kv,
                 __half* __restrict__ ctx)
{
    int warp = (blockIdx.x * 256 + threadIdx.x) >> 5;
    int lane = threadIdx.x & 31;
    int b = warp >> 2, h = warp & 3;

    size_t qoff = (size_t)b * DMODEL + h * DHEAD;
    uint4 qv = *(const uint4*)(q + qoff + lane * 8);

    float s[NTOK];
#pragma unroll
    for (int t = 0; t < NTOK; t++) {
        size_t koff = (size_t)(b * NTOK + t) * 2048 + h * DHEAD;
        uint4 kvec = *(const uint4*)(kv + koff + lane * 8);
        float d = dot8h(qv, kvec);
#pragma unroll
        for (int o = 16; o > 0; o >>= 1) d += __shfl_xor_sync(0xFFFFFFFFu, d, o);
        s[t] = d * (1.f / 16.f);   // 1/sqrt(256)
    }
    float m = fmaxf(fmaxf(s[0], s[1]), fmaxf(s[2], s[3]));
    float e[NTOK], sum = 0.f;
#pragma unroll
    for (int t = 0; t < NTOK; t++) { e[t] = expf(s[t] - m); sum += e[t]; }
    float inv = 1.f / sum;

    float cacc[8];
#pragma unroll
    for (int i = 0; i < 8; i++) cacc[i] = 0.f;
#pragma unroll
    for (int t = 0; t < NTOK; t++) {
        float a = e[t] * inv;
        size_t voff = (size_t)(b * NTOK + t) * 2048 + 1024 + h * DHEAD;
        uint4 vv = *(const uint4*)(kv + voff + lane * 8);
        const __half2* pv = (const __half2*)&vv;
#pragma unroll
        for (int i = 0; i < 4; i++) {
            float2 f = __half22float2(pv[i]);
            cacc[2 * i]     = fmaf(a, f.x, cacc[2 * i]);
            cacc[2 * i + 1] = fmaf(a, f.y, cacc[2 * i + 1]);
        }
    }
    uint4 ov;
    __half2* po = (__half2*)&ov;
#pragma unroll
    for (int i = 0; i < 4; i++)
        po[i] = __floats2half2_rn(cacc[2 * i], cacc[2 * i + 1]);
    *(uint4*)(ctx + qoff + lane * 8) = ov;
}

// ================= host launcher =================
extern "C" void kernel_launch(void* const* d_in, const int* in_sizes, int n_in,
                              void* d_out, int out_size)
{
    const float* embedding = (const float*)d_in[0];
    const float* physics   = (const float*)d_in[1];
    const float* pw1   = (const float*)d_in[2];
    const float* pb1   = (const float*)d_in[3];
    const float* pw2   = (const float*)d_in[4];
    const float* pb2   = (const float*)d_in[5];
    const float* lnq_g = (const float*)d_in[6];
    const float* lnq_b = (const float*)d_in[7];
    const float* lnkv_g = (const float*)d_in[8];
    const float* lnkv_b = (const float*)d_in[9];
    const float* wq = (const float*)d_in[10];
    const float* bq = (const float*)d_in[11];
    const float* wk = (const float*)d_in[12];
    const float* bk = (const float*)d_in[13];
    const float* wv = (const float*)d_in[14];
    const float* bv = (const float*)d_in[15];
    const float* wo = (const float*)d_in[16];
    const float* bo = (const float*)d_in[17];
    const float* ffn_g = (const float*)d_in[18];
    const float* ffn_b = (const float*)d_in[19];
    const float* fw1 = (const float*)d_in[20];
    const float* fb1 = (const float*)d_in[21];
    const float* fw2 = (const float*)d_in[22];
    const float* fb2 = (const float*)d_in[23];
    const float* gate = (const float*)d_in[24];
    float* out = (float*)d_out;

    __half *p_h, *p_physkv, *p_kvln, *p_qln, *p_qproj, *p_kv, *p_ctx, *p_fusedln, *p_ffh;
    __half *wt_pw2, *wt_q, *wt_kv, *wt_o, *wt_f1, *wt_f2;
    float  *p_fused, *p_bkv;
    cudaGetSymbolAddress((void**)&p_h, g_h);
    cudaGetSymbolAddress((void**)&p_physkv, g_physkv);
    cudaGetSymbolAddress((void**)&p_kvln, g_kvln);
    cudaGetSymbolAddress((void**)&p_qln, g_qln);
    cudaGetSymbolAddress((void**)&p_qproj, g_qproj);
    cudaGetSymbolAddress((void**)&p_kv, g_kv);
    cudaGetSymbolAddress((void**)&p_ctx, g_ctx);
    cudaGetSymbolAddress((void**)&p_fused, g_fused);
    cudaGetSymbolAddress((void**)&p_fusedln, g_fusedln);
    cudaGetSymbolAddress((void**)&p_ffh, g_ffh);
    cudaGetSymbolAddress((void**)&wt_pw2, g_wt_pw2);
    cudaGetSymbolAddress((void**)&wt_q, g_wt_q);
    cudaGetSymbolAddress((void**)&wt_kv, g_wt_kv);
    cudaGetSymbolAddress((void**)&wt_o, g_wt_o);
    cudaGetSymbolAddress((void**)&wt_f1, g_wt_f1);
    cudaGetSymbolAddress((void**)&wt_f2, g_wt_f2);
    cudaGetSymbolAddress((void**)&p_bkv, g_b_kv);

    cudaFuncSetAttribute(gemm_h<EPI_HALF>,   cudaFuncAttributeMaxDynamicSharedMemorySize, SMEM_TOT);
    cudaFuncSetAttribute(gemm_h<EPI_FUSED>,  cudaFuncAttributeMaxDynamicSharedMemorySize, SMEM_TOT);
    cudaFuncSetAttribute(gemm_h<EPI_GELU_H>, cudaFuncAttributeMaxDynamicSharedMemorySize, SMEM_TOT);
    cudaFuncSetAttribute(gemm_h<EPI_ADDOUT>, cudaFuncAttributeMaxDynamicSharedMemorySize, SMEM_TOT);

    // ---- two-stream fork/join (graph-capture-safe pattern) ----
    cudaStream_t s2;
    cudaStreamCreateWithFlags(&s2, cudaStreamNonBlocking);
    cudaEvent_t evF, evJ1, evJ2, evJ3;
    cudaEventCreateWithFlags(&evF,  cudaEventDisableTiming);
    cudaEventCreateWithFlags(&evJ1, cudaEventDisableTiming);
    cudaEventCreateWithFlags(&evJ2, cudaEventDisableTiming);
    cudaEventCreateWithFlags(&evJ3, cudaEventDisableTiming);

    // fork
    cudaEventRecord(evF, 0);
    cudaStreamWaitEvent(s2, evF, 0);

    // ---- side stream: independent weight prep + q branch ----
    transpose_w<<<dim3(DMODEL / 64, DMODEL / 64), 256, 0, s2>>>(wk, wt_kv, DMODEL, DMODEL);
    transpose_w<<<dim3(DMODEL / 64, DMODEL / 64), 256, 0, s2>>>(
        wv, wt_kv + (size_t)DMODEL * DMODEL, DMODEL, DMODEL);
    concat_bias<<<2, 1024, 0, s2>>>(bk, bv, p_bkv);
    cudaEventRecord(evJ1, s2);                       // wt_kv + bkv ready

    transpose_w<<<dim3(DMODEL / 64, DMODEL / 64), 256, 0, s2>>>(wq, wt_q, DMODEL, DMODEL);
    ln1024<float><<<BATCH, 256, 0, s2>>>(embedding, lnq_g, lnq_b, p_qln);
    gemm_h<EPI_HALF><<<dim3(DMODEL / 256, BATCH / 128), 256, SMEM_TOT, s2>>>(
        p_qln, wt_q, bq, p_qproj, nullptr, nullptr, DMODEL, DMODEL);
    cudaEventRecord(evJ2, s2);                       // qproj ready

    transpose_w<<<dim3(DMODEL / 64, DMODEL / 64), 256, 0, s2>>>(wo, wt_o, DMODEL, DMODEL);
    transpose_w<<<dim3(2048 / 64, DMODEL / 64), 256, 0, s2>>>(fw1, wt_f1, DMODEL, 2048);
    transpose_w<<<dim3(DMODEL / 64, 2048 / 64), 256, 0, s2>>>(fw2, wt_f2, 2048, DMODEL);
    cudaEventRecord(evJ3, s2);                       // wt_o/f1/f2 ready

    // ---- main stream: big chain ----
    transpose_w<<<dim3(DN / 64, DN / 64), 256>>>(pw2, wt_pw2, DN, DN);
    phys_mlp1<<<BATCH / 32, 256>>>(physics, pw1, pb1, p_h);

    // BIG GEMM: physkv = h @ pw2 + pb2 (fp16 out)
    gemm_h<EPI_HALF><<<dim3(DN / 256, BATCH / 128), 256, SMEM_TOT>>>(
        p_h, wt_pw2, pb2, p_physkv, nullptr, nullptr, DN, DN);

    // LN(physkv) -> fp16
    ln1024<__half><<<BATCH * NTOK, 256>>>(p_physkv, lnkv_g, lnkv_b, p_kvln);

    // kv projection (needs wt_kv + bkv from side stream)
    cudaStreamWaitEvent(0, evJ1, 0);
    gemm_h<EPI_HALF><<<dim3(2048 / 256, (BATCH * NTOK) / 128), 256, SMEM_TOT>>>(
        p_kvln, wt_kv, p_bkv, p_kv, nullptr, nullptr, 2048, DMODEL);

    // attention (needs qproj from side stream)
    cudaStreamWaitEvent(0, evJ2, 0);
    attn_kernel<<<(BATCH * NHEAD) / 8, 256>>>(p_qproj, p_kv, p_ctx);

    // join remaining weight prep, then output chain
    cudaStreamWaitEvent(0, evJ3, 0);

    // fused = embedding + sigmoid(gate) * (ctx @ wo + bo)  (fp32)
    gemm_h<EPI_FUSED><<<dim3(DMODEL / 256, BATCH / 128), 256, SMEM_TOT>>>(
        p_ctx, wt_o, bo, p_fused, embedding, gate, DMODEL, DMODEL);

    // LN(fused) -> fp16
    ln1024<float><<<BATCH, 256>>>(p_fused, ffn_g, ffn_b, p_fusedln);

    // ffh = gelu(fusedln @ fw1 + fb1) -> fp16
    gemm_h<EPI_GELU_H><<<dim3(2048 / 256, BATCH / 128), 256, SMEM_TOT>>>(
        p_fusedln, wt_f1, fb1, p_ffh, nullptr, nullptr, 2048, DMODEL);

    // out = fused + ffh @ fw2 + fb2  (fp32)
    gemm_h<EPI_ADDOUT><<<dim3(DMODEL / 256, BATCH / 128), 256, SMEM_TOT>>>(
        p_ffh, wt_f2, fb2, out, p_fused, nullptr, DMODEL, 2048);
}

// round 13
// speedup vs baseline: 1.2005x; 1.0091x over previous
#include <cuda_runtime.h>
#include <cuda_fp16.h>
#include <cstdint>
#include <cstddef>

// ---------------- problem constants ----------------
#define BATCH   16384
#define HB      8192                 // BATCH/2 (half-M pipelining)
#define DMODEL  1024
#define PHYSD   11
#define NTOK    4
#define NHEAD   4
#define DHEAD   256
#define DN      4096
#define LN_EPS  1e-5f

// ---------------- device scratch (allocation-free rule) ----------------
__device__ __half g_h      [(size_t)BATCH * DN];
__device__ __half g_physkv [(size_t)BATCH * DN];
__device__ __half g_kvln   [(size_t)BATCH * DN];
__device__ __half g_qln    [(size_t)BATCH * DMODEL];
__device__ __half g_qproj  [(size_t)BATCH * DMODEL];
__device__ __half g_kv     [(size_t)BATCH * NTOK * 2048];   // [k(1024)|v(1024)] per token
__device__ __half g_ctx    [(size_t)BATCH * DMODEL];
__device__ float  g_fused  [(size_t)BATCH * DMODEL];
__device__ __half g_fusedln[(size_t)BATCH * DMODEL];
__device__ __half g_ffh    [(size_t)BATCH * 2048];
// transposed weights [N][K] fp16
__device__ __half g_wt_pw2 [(size_t)DN * DN];
__device__ __half g_wt_q   [(size_t)DMODEL * DMODEL];
__device__ __half g_wt_kv  [(size_t)2048 * DMODEL];
__device__ __half g_wt_o   [(size_t)DMODEL * DMODEL];
__device__ __half g_wt_f1  [(size_t)2048 * DMODEL];
__device__ __half g_wt_f2  [(size_t)DMODEL * 2048];
__device__ float  g_b_kv   [2048];

// ---------------- helpers ----------------
__device__ __forceinline__ float gelu_f(float x) {
    float x3 = x * x * x;
    float t  = tanhf(0.79788456080286535588f * (x + 0.044715f * x3));
    return 0.5f * x * (1.0f + t);
}
__device__ __forceinline__ void cpa16(uint32_t sdst, const void* gsrc) {
    asm volatile("cp.async.cg.shared.global [%0], [%1], 16;\n" :: "r"(sdst), "l"(gsrc));
}
__device__ __forceinline__ void ldsm4(uint32_t& r0, uint32_t& r1, uint32_t& r2, uint32_t& r3,
                                      uint32_t addr) {
    asm volatile("ldmatrix.sync.aligned.m8n8.x4.shared.b16 {%0,%1,%2,%3}, [%4];"
                 : "=r"(r0), "=r"(r1), "=r"(r2), "=r"(r3) : "r"(addr));
}

// ================= fp16 GEMM: out[M,N] = A[M,K] @ Wt[N,K]^T + bias =================
// BM=128 BN=256 BK=32, 256 threads = 8 warps (2M x 4N), warp tile 64x64.
// fp32-accum m16n8k16, ldmatrix, 4-stage cp.async, 1 barrier/k-tile. (R8 config.)
enum { EPI_F32 = 0, EPI_HALF = 1, EPI_FUSED = 2, EPI_GELU_H = 3, EPI_ADDOUT = 4 };

#define LDK        40                         // halves per smem row (pad)
#define A_BYTES    (128 * LDK * 2)            // 10240
#define B_BYTES    (256 * LDK * 2)            // 20480
#define STAGE_B    (A_BYTES + B_BYTES)        // 30720
#define NSTAGE     4
#define SMEM_TOT   (STAGE_B * NSTAGE)         // 122880

template <int EPI>
__global__ __launch_bounds__(256, 1)
void gemm_h(const __half* __restrict__ A, const __half* __restrict__ Wt,
            const float* __restrict__ bias, void* __restrict__ outp,
            const float* __restrict__ aux, const float* __restrict__ gatep,
            int N, int K)
{
    extern __shared__ char smem[];
    const uint32_t sb = (uint32_t)__cvta_generic_to_shared(smem);

    const int tid  = threadIdx.x;
    const int lane = tid & 31;
    const int wid  = tid >> 5;
    const int wm   = wid >> 2;          // 0..1
    const int wn   = wid & 3;           // 0..3
    const int g    = lane >> 2;         // 0..7
    const int c    = lane & 3;          // 0..3
    const int m0   = blockIdx.y * 128;
    const int n0   = blockIdx.x * 256;

    const int a_row  = wm * 64 + (lane & 15);                      // + mi*16
    const int a_koff = (lane >> 4) << 3;                           // 0 or 8
    const int b_row  = wn * 64 + ((lane >> 4) << 3) + (lane & 7);  // + nj*16
    const int b_koff = lane & 8;                                   // 0 or 8

    float acc[4][8][4];
#pragma unroll
    for (int mi = 0; mi < 4; mi++)
#pragma unroll
        for (int ni = 0; ni < 8; ni++)
#pragma unroll
            for (int e = 0; e < 4; e++) acc[mi][ni][e] = 0.f;

    const int nt = K >> 5;

    auto fill = [&](int s, int kt) {
        const uint32_t a0 = sb + (uint32_t)s * STAGE_B;
        const uint32_t b0 = a0 + A_BYTES;
        const __half* Ag = A  + (size_t)m0 * K + kt * 32;
        const __half* Bg = Wt + (size_t)n0 * K + kt * 32;
#pragma unroll
        for (int i = 0; i < 2; i++) {
            int idx = tid + 256 * i;
            int r = idx >> 2, c8 = idx & 3;
            cpa16(a0 + (uint32_t)(r * LDK + c8 * 8) * 2, Ag + (size_t)r * K + c8 * 8);
        }
#pragma unroll
        for (int i = 0; i < 4; i++) {
            int idx = tid + 256 * i;
            int r = idx >> 2, c8 = idx & 3;
            cpa16(b0 + (uint32_t)(r * LDK + c8 * 8) * 2, Bg + (size_t)r * K + c8 * 8);
        }
        asm volatile("cp.async.commit_group;" ::: "memory");
    };

    fill(0, 0); fill(1, 1); fill(2, 2);

    for (int kt = 0; kt < nt; kt++) {
        const int rem = nt - 1 - kt;
        if (rem >= 2)      asm volatile("cp.async.wait_group 2;" ::: "memory");
        else if (rem == 1) asm volatile("cp.async.wait_group 1;" ::: "memory");
        else               asm volatile("cp.async.wait_group 0;" ::: "memory");
        __syncthreads();

        if (kt + 3 < nt) fill((kt + 3) & 3, kt + 3);

        const int s = kt & 3;
        const uint32_t aBase = sb + (uint32_t)s * STAGE_B;
        const uint32_t bBase = aBase + A_BYTES;

#pragma unroll
        for (int ks = 0; ks < 2; ks++) {
            const int k0 = ks * 16;
            uint32_t af[4][4];
#pragma unroll
            for (int mi = 0; mi < 4; mi++)
                ldsm4(af[mi][0], af[mi][1], af[mi][2], af[mi][3],
                      aBase + (uint32_t)((a_row + mi * 16) * LDK + k0 + a_koff) * 2);
            uint32_t bf[8][2];
#pragma unroll
            for (int nj = 0; nj < 4; nj++) {
                uint32_t r0, r1, r2, r3;
                ldsm4(r0, r1, r2, r3,
                      bBase + (uint32_t)((b_row + nj * 16) * LDK + k0 + b_koff) * 2);
                bf[2 * nj][0] = r0; bf[2 * nj][1] = r1;
                bf[2 * nj + 1][0] = r2; bf[2 * nj + 1][1] = r3;
            }
#pragma unroll
            for (int mi = 0; mi < 4; mi++)
#pragma unroll
                for (int ni = 0; ni < 8; ni++) {
                    asm volatile(
                        "mma.sync.aligned.m16n8k16.row.col.f32.f16.f16.f32 "
                        "{%0,%1,%2,%3}, {%4,%5,%6,%7}, {%8,%9}, {%0,%1,%2,%3};\n"
                        : "+f"(acc[mi][ni][0]), "+f"(acc[mi][ni][1]),
                          "+f"(acc[mi][ni][2]), "+f"(acc[mi][ni][3])
                        : "r"(af[mi][0]), "r"(af[mi][1]), "r"(af[mi][2]), "r"(af[mi][3]),
                          "r"(bf[ni][0]), "r"(bf[ni][1]));
                }
        }
    }

    // ---------------- epilogue ----------------
    float sig = 1.f;
    if (EPI == EPI_FUSED) sig = 1.f / (1.f + expf(-gatep[0]));

#pragma unroll
    for (int mi = 0; mi < 4; mi++) {
#pragma unroll
        for (int ni = 0; ni < 8; ni++) {
            const int col = n0 + wn * 64 + ni * 8 + 2 * c;
            const float b0 = bias[col], b1 = bias[col + 1];
#pragma unroll
            for (int half_ = 0; half_ < 2; half_++) {
                const int row = m0 + wm * 64 + mi * 16 + g + half_ * 8;
                const size_t oi = (size_t)row * N + col;
                float v0 = acc[mi][ni][half_ * 2 + 0] + b0;
                float v1 = acc[mi][ni][half_ * 2 + 1] + b1;
                if (EPI == EPI_F32) {
                    *(float2*)((float*)outp + oi) = make_float2(v0, v1);
                } else if (EPI == EPI_HALF) {
                    *(__half2*)((__half*)outp + oi) = __floats2half2_rn(v0, v1);
                } else if (EPI == EPI_FUSED) {
                    float2 a2 = *(const float2*)(aux + oi);
                    *(float2*)((float*)outp + oi) =
                        make_float2(a2.x + sig * v0, a2.y + sig * v1);
                } else if (EPI == EPI_GELU_H) {
                    *(__half2*)((__half*)outp + oi) =
                        __floats2half2_rn(gelu_f(v0), gelu_f(v1));
                } else { // EPI_ADDOUT
                    float2 a2 = *(const float2*)(aux + oi);
                    *(float2*)((float*)outp + oi) = make_float2(a2.x + v0, a2.y + v1);
                }
            }
        }
    }
}

// ================= weight transpose 64x64: Wt[n][k] = (half)W[k][n] =================
__global__ __launch_bounds__(256)
void transpose_w(const float* __restrict__ in, __half* __restrict__ out,
                 int rows, int cols)
{
    __shared__ float t[64][65];
    const int bx = blockIdx.x * 64;   // input col tile
    const int by = blockIdx.y * 64;   // input row tile
#pragma unroll
    for (int i = threadIdx.x; i < 1024; i += 256) {
        int r = i >> 4, c4 = (i & 15) * 4;
        float4 v = *(const float4*)&in[(size_t)(by + r) * cols + bx + c4];
        t[r][c4] = v.x; t[r][c4 + 1] = v.y; t[r][c4 + 2] = v.z; t[r][c4 + 3] = v.w;
    }
    __syncthreads();
#pragma unroll
    for (int i = threadIdx.x; i < 1024; i += 256) {
        int cc = i >> 4, r4 = (i & 15) * 4;
        __half2 h0 = __floats2half2_rn(t[r4][cc],     t[r4 + 1][cc]);
        __half2 h1 = __floats2half2_rn(t[r4 + 2][cc], t[r4 + 3][cc]);
        uint2 pk = make_uint2(*(uint32_t*)&h0, *(uint32_t*)&h1);
        *(uint2*)&out[(size_t)(bx + cc) * rows + by + r4] = pk;
    }
}

// ================= bias concat =================
__global__ void concat_bias(const float* __restrict__ a, const float* __restrict__ b,
                            float* __restrict__ o)
{
    int i = blockIdx.x * blockDim.x + threadIdx.x;
    o[i] = (i < 1024) ? a[i] : b[i - 1024];
}

// ================= phys MLP stage 1 (32 rows per block, pw1 reused) =================
__global__ __launch_bounds__(256)
void phys_mlp1(const float* __restrict__ phys, const float* __restrict__ pw1,
               const float* __restrict__ pb1, __half* __restrict__ out)
{
    __shared__ float p[32][PHYSD + 1];
    const int b0 = blockIdx.x * 32;
    const int tid = threadIdx.x;
    for (int i = tid; i < 32 * PHYSD; i += 256) {
        int r = i / PHYSD, k = i % PHYSD;
        p[r][k] = phys[(size_t)(b0 + r) * PHYSD + k];
    }
    __syncthreads();

    for (int n = tid; n < DN; n += 256) {
        float w[PHYSD];
#pragma unroll
        for (int k = 0; k < PHYSD; k++) w[k] = pw1[(size_t)k * DN + n];
        const float bb = pb1[n];
#pragma unroll 4
        for (int r = 0; r < 32; r++) {
            float s = bb;
#pragma unroll
            for (int k = 0; k < PHYSD; k++) s = fmaf(p[r][k], w[k], s);
            out[(size_t)(b0 + r) * DN + n] = __float2half_rn(gelu_f(s));
        }
    }
}

// ================= LayerNorm (D=1024), templated input, fp16 out =================
template <typename IT>
__global__ __launch_bounds__(256)
void ln1024(const IT* __restrict__ x, const float* __restrict__ gg,
            const float* __restrict__ bb, __half* __restrict__ out)
{
    __shared__ float red1[8], red2[8];
    const int row = blockIdx.x;
    const int tid = threadIdx.x;
    const int lane = tid & 31, wid = tid >> 5;

    float4 v;
    if (sizeof(IT) == 4) {
        v = *(const float4*)((const float*)x + (size_t)row * DMODEL + tid * 4);
    } else {
        uint2 pk = *(const uint2*)((const __half*)x + (size_t)row * DMODEL + tid * 4);
        float2 f0 = __half22float2(*(__half2*)&pk.x);
        float2 f1 = __half22float2(*(__half2*)&pk.y);
        v = make_float4(f0.x, f0.y, f1.x, f1.y);
    }
    float s1 = v.x + v.y + v.z + v.w;
    float s2 = v.x * v.x + v.y * v.y + v.z * v.z + v.w * v.w;
#pragma unroll
    for (int o = 16; o > 0; o >>= 1) {
        s1 += __shfl_down_sync(0xFFFFFFFFu, s1, o);
        s2 += __shfl_down_sync(0xFFFFFFFFu, s2, o);
    }
    if (lane == 0) { red1[wid] = s1; red2[wid] = s2; }
    __syncthreads();
    if (tid == 0) {
        float a = 0.f, b2 = 0.f;
#pragma unroll
        for (int i = 0; i < 8; i++) { a += red1[i]; b2 += red2[i]; }
        red1[0] = a; red2[0] = b2;
    }
    __syncthreads();
    const float mu  = red1[0] * (1.f / DMODEL);
    const float var = red2[0] * (1.f / DMODEL) - mu * mu;
    const float rs  = rsqrtf(var + LN_EPS);

    float4 gv = *(const float4*)(gg + tid * 4);
    float4 bv = *(const float4*)(bb + tid * 4);
    __half2 o0 = __floats2half2_rn((v.x - mu) * rs * gv.x + bv.x,
                                   (v.y - mu) * rs * gv.y + bv.y);
    __half2 o1 = __floats2half2_rn((v.z - mu) * rs * gv.z + bv.z,
                                   (v.w - mu) * rs * gv.w + bv.w);
    uint2 pk = make_uint2(*(uint32_t*)&o0, *(uint32_t*)&o1);
    *(uint2*)(out + (size_t)row * DMODEL + tid * 4) = pk;
}

// ================= attention: warp per (b, head), packed kv =================
__device__ __forceinline__ float dot8h(uint4 a, uint4 b) {
    const __half2* pa = (const __half2*)&a;
    const __half2* pb = (const __half2*)&b;
    float s = 0.f;
#pragma unroll
    for (int i = 0; i < 4; i++) {
        float2 fa = __half22float2(pa[i]);
        float2 fb = __half22float2(pb[i]);
        s = fmaf(fa.x, fb.x, s);
        s = fmaf(fa.y, fb.y, s);
    }
    return s;
}

__global__ __launch_bounds__(256)
void attn_kernel(const __half* __restrict__ q, const __half* __restrict__ kv,
                 __half* __restrict__ ctx)
{
    int warp = (blockIdx.x * 256 + threadIdx.x) >> 5;
    int lane = threadIdx.x & 31;
    int b = warp >> 2, h = warp & 3;

    size_t qoff = (size_t)b * DMODEL + h * DHEAD;
    uint4 qv = *(const uint4*)(q + qoff + lane * 8);

    float s[NTOK];
#pragma unroll
    for (int t = 0; t < NTOK; t++) {
        size_t koff = (size_t)(b * NTOK + t) * 2048 + h * DHEAD;
        uint4 kvec = *(const uint4*)(kv + koff + lane * 8);
        float d = dot8h(qv, kvec);
#pragma unroll
        for (int o = 16; o > 0; o >>= 1) d += __shfl_xor_sync(0xFFFFFFFFu, d, o);
        s[t] = d * (1.f / 16.f);   // 1/sqrt(256)
    }
    float m = fmaxf(fmaxf(s[0], s[1]), fmaxf(s[2], s[3]));
    float e[NTOK], sum = 0.f;
#pragma unroll
    for (int t = 0; t < NTOK; t++) { e[t] = expf(s[t] - m); sum += e[t]; }
    float inv = 1.f / sum;

    float cacc[8];
#pragma unroll
    for (int i = 0; i < 8; i++) cacc[i] = 0.f;
#pragma unroll
    for (int t = 0; t < NTOK; t++) {
        float a = e[t] * inv;
        size_t voff = (size_t)(b * NTOK + t) * 2048 + 1024 + h * DHEAD;
        uint4 vv = *(const uint4*)(kv + voff + lane * 8);
        const __half2* pv = (const __half2*)&vv;
#pragma unroll
        for (int i = 0; i < 4; i++) {
            float2 f = __half22float2(pv[i]);
            cacc[2 * i]     = fmaf(a, f.x, cacc[2 * i]);
            cacc[2 * i + 1] = fmaf(a, f.y, cacc[2 * i + 1]);
        }
    }
    uint4 ov;
    __half2* po = (__half2*)&ov;
#pragma unroll
    for (int i = 0; i < 4; i++)
        po[i] = __floats2half2_rn(cacc[2 * i], cacc[2 * i + 1]);
    *(uint4*)(ctx + qoff + lane * 8) = ov;
}

// ================= host launcher =================
extern "C" void kernel_launch(void* const* d_in, const int* in_sizes, int n_in,
                              void* d_out, int out_size)
{
    const float* embedding = (const float*)d_in[0];
    const float* physics   = (const float*)d_in[1];
    const float* pw1   = (const float*)d_in[2];
    const float* pb1   = (const float*)d_in[3];
    const float* pw2   = (const float*)d_in[4];
    const float* pb2   = (const float*)d_in[5];
    const float* lnq_g = (const float*)d_in[6];
    const float* lnq_b = (const float*)d_in[7];
    const float* lnkv_g = (const float*)d_in[8];
    const float* lnkv_b = (const float*)d_in[9];
    const float* wq = (const float*)d_in[10];
    const float* bq = (const float*)d_in[11];
    const float* wk = (const float*)d_in[12];
    const float* bk = (const float*)d_in[13];
    const float* wv = (const float*)d_in[14];
    const float* bv = (const float*)d_in[15];
    const float* wo = (const float*)d_in[16];
    const float* bo = (const float*)d_in[17];
    const float* ffn_g = (const float*)d_in[18];
    const float* ffn_b = (const float*)d_in[19];
    const float* fw1 = (const float*)d_in[20];
    const float* fb1 = (const float*)d_in[21];
    const float* fw2 = (const float*)d_in[22];
    const float* fb2 = (const float*)d_in[23];
    const float* gate = (const float*)d_in[24];
    float* out = (float*)d_out;

    __half *p_h, *p_physkv, *p_kvln, *p_qln, *p_qproj, *p_kv, *p_ctx, *p_fusedln, *p_ffh;
    __half *wt_pw2, *wt_q, *wt_kv, *wt_o, *wt_f1, *wt_f2;
    float  *p_fused, *p_bkv;
    cudaGetSymbolAddress((void**)&p_h, g_h);
    cudaGetSymbolAddress((void**)&p_physkv, g_physkv);
    cudaGetSymbolAddress((void**)&p_kvln, g_kvln);
    cudaGetSymbolAddress((void**)&p_qln, g_qln);
    cudaGetSymbolAddress((void**)&p_qproj, g_qproj);
    cudaGetSymbolAddress((void**)&p_kv, g_kv);
    cudaGetSymbolAddress((void**)&p_ctx, g_ctx);
    cudaGetSymbolAddress((void**)&p_fused, g_fused);
    cudaGetSymbolAddress((void**)&p_fusedln, g_fusedln);
    cudaGetSymbolAddress((void**)&p_ffh, g_ffh);
    cudaGetSymbolAddress((void**)&wt_pw2, g_wt_pw2);
    cudaGetSymbolAddress((void**)&wt_q, g_wt_q);
    cudaGetSymbolAddress((void**)&wt_kv, g_wt_kv);
    cudaGetSymbolAddress((void**)&wt_o, g_wt_o);
    cudaGetSymbolAddress((void**)&wt_f1, g_wt_f1);
    cudaGetSymbolAddress((void**)&wt_f2, g_wt_f2);
    cudaGetSymbolAddress((void**)&p_bkv, g_b_kv);

    cudaFuncSetAttribute(gemm_h<EPI_HALF>,   cudaFuncAttributeMaxDynamicSharedMemorySize, SMEM_TOT);
    cudaFuncSetAttribute(gemm_h<EPI_FUSED>,  cudaFuncAttributeMaxDynamicSharedMemorySize, SMEM_TOT);
    cudaFuncSetAttribute(gemm_h<EPI_GELU_H>, cudaFuncAttributeMaxDynamicSharedMemorySize, SMEM_TOT);
    cudaFuncSetAttribute(gemm_h<EPI_ADDOUT>, cudaFuncAttributeMaxDynamicSharedMemorySize, SMEM_TOT);

    // ---- streams / events (graph-capture fork/join) ----
    cudaStream_t s2;
    cudaStreamCreateWithFlags(&s2, cudaStreamNonBlocking);
    cudaEvent_t evF, evPW2, evKV, evW, evG1, evG2, evLN1, evLN2,
                evKV1, evKV2, evA1, evA2, evFU1, evFU2, evL1, evL2;
    cudaEvent_t* evs[] = {&evF, &evPW2, &evKV, &evW, &evG1, &evG2, &evLN1, &evLN2,
                          &evKV1, &evKV2, &evA1, &evA2, &evFU1, &evFU2, &evL1, &evL2};
    for (auto e : evs) cudaEventCreateWithFlags(e, cudaEventDisableTiming);

    // fork
    cudaEventRecord(evF, 0);
    cudaStreamWaitEvent(s2, evF, 0);

    // ---- side stream: weight prep + q branch ----
    transpose_w<<<dim3(DN / 64, DN / 64), 256, 0, s2>>>(pw2, wt_pw2, DN, DN);
    cudaEventRecord(evPW2, s2);
    transpose_w<<<dim3(DMODEL / 64, DMODEL / 64), 256, 0, s2>>>(wk, wt_kv, DMODEL, DMODEL);
    transpose_w<<<dim3(DMODEL / 64, DMODEL / 64), 256, 0, s2>>>(
        wv, wt_kv + (size_t)DMODEL * DMODEL, DMODEL, DMODEL);
    concat_bias<<<2, 1024, 0, s2>>>(bk, bv, p_bkv);
    cudaEventRecord(evKV, s2);
    transpose_w<<<dim3(DMODEL / 64, DMODEL / 64), 256, 0, s2>>>(wq, wt_q, DMODEL, DMODEL);
    ln1024<float><<<BATCH, 256, 0, s2>>>(embedding, lnq_g, lnq_b, p_qln);
    gemm_h<EPI_HALF><<<dim3(DMODEL / 256, BATCH / 128), 256, SMEM_TOT, s2>>>(
        p_qln, wt_q, bq, p_qproj, nullptr, nullptr, DMODEL, DMODEL);
    transpose_w<<<dim3(DMODEL / 64, DMODEL / 64), 256, 0, s2>>>(wo, wt_o, DMODEL, DMODEL);
    transpose_w<<<dim3(2048 / 64, DMODEL / 64), 256, 0, s2>>>(fw1, wt_f1, DMODEL, 2048);
    transpose_w<<<dim3(DMODEL / 64, 2048 / 64), 256, 0, s2>>>(fw2, wt_f2, 2048, DMODEL);
    cudaEventRecord(evW, s2);    // covers qproj + all remaining transposes

    // ---- main: phys stage 1 (parallel with pw2 transpose on s2) ----
    phys_mlp1<<<BATCH / 32, 256>>>(physics, pw1, pb1, p_h);

    // ---- BIG GEMM in half-M, lnkv of half1 overlaps half2 ----
    cudaStreamWaitEvent(0, evPW2, 0);
    gemm_h<EPI_HALF><<<dim3(DN / 256, HB / 128), 256, SMEM_TOT>>>(
        p_h, wt_pw2, pb2, p_physkv, nullptr, nullptr, DN, DN);
    cudaEventRecord(evG1, 0);
    gemm_h<EPI_HALF><<<dim3(DN / 256, HB / 128), 256, SMEM_TOT>>>(
        p_h + (size_t)HB * DN, wt_pw2, pb2, p_physkv + (size_t)HB * DN,
        nullptr, nullptr, DN, DN);
    cudaEventRecord(evG2, 0);

    cudaStreamWaitEvent(s2, evG1, 0);
    ln1024<__half><<<HB * NTOK, 256, 0, s2>>>(p_physkv, lnkv_g, lnkv_b, p_kvln);
    cudaEventRecord(evLN1, s2);
    cudaStreamWaitEvent(s2, evG2, 0);
    ln1024<__half><<<HB * NTOK, 256, 0, s2>>>(
        p_physkv + (size_t)HB * DN, lnkv_g, lnkv_b, p_kvln + (size_t)HB * DN);
    cudaEventRecord(evLN2, s2);

    // ---- kv GEMM in half-M, attn of half1 overlaps half2 ----
    cudaStreamWaitEvent(0, evLN1, 0);
    cudaStreamWaitEvent(0, evKV, 0);
    gemm_h<EPI_HALF><<<dim3(2048 / 256, (HB * NTOK) / 128), 256, SMEM_TOT>>>(
        p_kvln, wt_kv, p_bkv, p_kv, nullptr, nullptr, 2048, DMODEL);
    cudaEventRecord(evKV1, 0);
    cudaStreamWaitEvent(0, evLN2, 0);
    gemm_h<EPI_HALF><<<dim3(2048 / 256, (HB * NTOK) / 128), 256, SMEM_TOT>>>(
        p_kvln + (size_t)HB * NTOK * DMODEL, wt_kv, p_bkv,
        p_kv + (size_t)HB * NTOK * 2048, nullptr, nullptr, 2048, DMODEL);
    cudaEventRecord(evKV2, 0);

    cudaStreamWaitEvent(s2, evKV1, 0);   // qproj already ordered on s2
    attn_kernel<<<(HB * NHEAD) / 8, 256, 0, s2>>>(p_qproj, p_kv, p_ctx);
    cudaEventRecord(evA1, s2);
    cudaStreamWaitEvent(s2, evKV2, 0);
    attn_kernel<<<(HB * NHEAD) / 8, 256, 0, s2>>>(
        p_qproj + (size_t)HB * DMODEL, p_kv + (size_t)HB * NTOK * 2048,
        p_ctx + (size_t)HB * DMODEL);
    cudaEventRecord(evA2, s2);

    // ---- fused GEMM in half-M, ln_fused of half1 overlaps half2 ----
    cudaStreamWaitEvent(0, evA1, 0);
    cudaStreamWaitEvent(0, evW, 0);
    gemm_h<EPI_FUSED><<<dim3(DMODEL / 256, HB / 128), 256, SMEM_TOT>>>(
        p_ctx, wt_o, bo, p_fused, embedding, gate, DMODEL, DMODEL);
    cudaEventRecord(evFU1, 0);
    cudaStreamWaitEvent(0, evA2, 0);
    gemm_h<EPI_FUSED><<<dim3(DMODEL / 256, HB / 128), 256, SMEM_TOT>>>(
        p_ctx + (size_t)HB * DMODEL, wt_o, bo, p_fused + (size_t)HB * DMODEL,
        embedding + (size_t)HB * DMODEL, gate, DMODEL, DMODEL);
    cudaEventRecord(evFU2, 0);

    cudaStreamWaitEvent(s2, evFU1, 0);
    ln1024<float><<<HB, 256, 0, s2>>>(p_fused, ffn_g, ffn_b, p_fusedln);
    cudaEventRecord(evL1, s2);
    cudaStreamWaitEvent(s2, evFU2, 0);
    ln1024<float><<<HB, 256, 0, s2>>>(
        p_fused + (size_t)HB * DMODEL, ffn_g, ffn_b, p_fusedln + (size_t)HB * DMODEL);
    cudaEventRecord(evL2, s2);

    // ---- FFN (unsplit: splitting gelu GEMM costs a wave) ----
    cudaStreamWaitEvent(0, evL1, 0);
    cudaStreamWaitEvent(0, evL2, 0);
    gemm_h<EPI_GELU_H><<<dim3(2048 / 256, BATCH / 128), 256, SMEM_TOT>>>(
        p_fusedln, wt_f1, fb1, p_ffh, nullptr, nullptr, 2048, DMODEL);
    gemm_h<EPI_ADDOUT><<<dim3(DMODEL / 256, BATCH / 128), 256, SMEM_TOT>>>(
        p_ffh, wt_f2, fb2, out, p_fused, nullptr, DMODEL, 2048);
}

// round 14
// speedup vs baseline: 1.3680x; 1.1395x over previous
#include <cuda_runtime.h>
#include <cuda_fp16.h>
#include <cstdint>
#include <cstddef>

// ---------------- problem constants ----------------
#define BATCH   16384
#define HB      8192                 // BATCH/2 (half-M pipelining)
#define DMODEL  1024
#define PHYSD   11
#define NTOK    4
#define NHEAD   4
#define DHEAD   256
#define DN      4096
#define LN_EPS  1e-5f

// ---------------- device scratch (allocation-free rule) ----------------
__device__ __half g_h      [(size_t)BATCH * DN];
__device__ __half g_physkv [(size_t)BATCH * DN];
__device__ __half g_kvln   [(size_t)BATCH * DN];
__device__ __half g_qln    [(size_t)BATCH * DMODEL];
__device__ __half g_qproj  [(size_t)BATCH * DMODEL];
__device__ __half g_kv     [(size_t)BATCH * NTOK * 2048];   // [k(1024)|v(1024)] per token
__device__ __half g_ctx    [(size_t)BATCH * DMODEL];
__device__ float  g_fused  [(size_t)BATCH * DMODEL];
__device__ __half g_fusedln[(size_t)BATCH * DMODEL];
__device__ __half g_ffh    [(size_t)BATCH * 2048];
// transposed weights [N][K] fp16
__device__ __half g_wt_pw2 [(size_t)DN * DN];
__device__ __half g_wt_q   [(size_t)DMODEL * DMODEL];
__device__ __half g_wt_kv  [(size_t)2048 * DMODEL];
__device__ __half g_wt_o   [(size_t)DMODEL * DMODEL];
__device__ __half g_wt_f1  [(size_t)2048 * DMODEL];
__device__ __half g_wt_f2  [(size_t)DMODEL * 2048];
__device__ float  g_b_kv   [2048];

// ---------------- helpers ----------------
__device__ __forceinline__ float gelu_f(float x) {
    float x3 = x * x * x;
    float t  = tanhf(0.79788456080286535588f * (x + 0.044715f * x3));
    return 0.5f * x * (1.0f + t);
}
__device__ __forceinline__ void cpa16(uint32_t sdst, const void* gsrc) {
    asm volatile("cp.async.cg.shared.global [%0], [%1], 16;\n" :: "r"(sdst), "l"(gsrc));
}
__device__ __forceinline__ void ldsm4(uint32_t& r0, uint32_t& r1, uint32_t& r2, uint32_t& r3,
                                      uint32_t addr) {
    asm volatile("ldmatrix.sync.aligned.m8n8.x4.shared.b16 {%0,%1,%2,%3}, [%4];"
                 : "=r"(r0), "=r"(r1), "=r"(r2), "=r"(r3) : "r"(addr));
}

// ================= fp16 GEMM: out[M,N] = A[M,K] @ Wt[N,K]^T + bias =================
// BM=128 BN=256 BK=64, 256 threads = 8 warps (2M x 4N), warp tile 64x64.
// fp32-accum m16n8k16, ldmatrix, 3-stage cp.async ring, 1 barrier per 64-K tile
// (half the barrier/fill frequency of the BK=32 version; same mma order).
enum { EPI_F32 = 0, EPI_HALF = 1, EPI_FUSED = 2, EPI_GELU_H = 3, EPI_ADDOUT = 4 };

#define LDK        72                         // halves per smem row (64 + 8 pad)
#define A_BYTES    (128 * LDK * 2)            // 18432
#define B_BYTES    (256 * LDK * 2)            // 36864
#define STAGE_B    (A_BYTES + B_BYTES)        // 55296
#define NSTAGE     3
#define SMEM_TOT   (STAGE_B * NSTAGE)         // 165888

template <int EPI>
__global__ __launch_bounds__(256, 1)
void gemm_h(const __half* __restrict__ A, const __half* __restrict__ Wt,
            const float* __restrict__ bias, void* __restrict__ outp,
            const float* __restrict__ aux, const float* __restrict__ gatep,
            int N, int K)
{
    extern __shared__ char smem[];
    const uint32_t sb = (uint32_t)__cvta_generic_to_shared(smem);

    const int tid  = threadIdx.x;
    const int lane = tid & 31;
    const int wid  = tid >> 5;
    const int wm   = wid >> 2;          // 0..1
    const int wn   = wid & 3;           // 0..3
    const int g    = lane >> 2;         // 0..7
    const int c    = lane & 3;          // 0..3
    const int m0   = blockIdx.y * 128;
    const int n0   = blockIdx.x * 256;

    const int a_row  = wm * 64 + (lane & 15);                      // + mi*16
    const int a_koff = (lane >> 4) << 3;                           // 0 or 8
    const int b_row  = wn * 64 + ((lane >> 4) << 3) + (lane & 7);  // + nj*16
    const int b_koff = lane & 8;                                   // 0 or 8

    float acc[4][8][4];
#pragma unroll
    for (int mi = 0; mi < 4; mi++)
#pragma unroll
        for (int ni = 0; ni < 8; ni++)
#pragma unroll
            for (int e = 0; e < 4; e++) acc[mi][ni][e] = 0.f;

    const int nt = K >> 6;              // 64-K tiles

    auto fill = [&](int s, int kt) {
        const uint32_t a0 = sb + (uint32_t)s * STAGE_B;
        const uint32_t b0 = a0 + A_BYTES;
        const __half* Ag = A  + (size_t)m0 * K + kt * 64;
        const __half* Bg = Wt + (size_t)n0 * K + kt * 64;
#pragma unroll
        for (int i = 0; i < 4; i++) {
            int idx = tid + 256 * i;          // 0..1023  (128 rows x 8 chunks)
            int r = idx >> 3, c8 = idx & 7;
            cpa16(a0 + (uint32_t)(r * LDK + c8 * 8) * 2, Ag + (size_t)r * K + c8 * 8);
        }
#pragma unroll
        for (int i = 0; i < 8; i++) {
            int idx = tid + 256 * i;          // 0..2047  (256 rows x 8 chunks)
            int r = idx >> 3, c8 = idx & 7;
            cpa16(b0 + (uint32_t)(r * LDK + c8 * 8) * 2, Bg + (size_t)r * K + c8 * 8);
        }
        asm volatile("cp.async.commit_group;" ::: "memory");
    };

    fill(0, 0); fill(1, 1);

    int s_cur = 0, s_fill = 2;
    for (int kt = 0; kt < nt; kt++) {
        if (kt + 1 < nt) asm volatile("cp.async.wait_group 1;" ::: "memory");
        else             asm volatile("cp.async.wait_group 0;" ::: "memory");
        __syncthreads();

        if (kt + 2 < nt) {
            fill(s_fill, kt + 2);
            s_fill = (s_fill == 2) ? 0 : s_fill + 1;
        }

        const uint32_t aBase = sb + (uint32_t)s_cur * STAGE_B;
        const uint32_t bBase = aBase + A_BYTES;
        s_cur = (s_cur == 2) ? 0 : s_cur + 1;

#pragma unroll
        for (int ks = 0; ks < 4; ks++) {
            const int k0 = ks * 16;
            uint32_t af[4][4];
#pragma unroll
            for (int mi = 0; mi < 4; mi++)
                ldsm4(af[mi][0], af[mi][1], af[mi][2], af[mi][3],
                      aBase + (uint32_t)((a_row + mi * 16) * LDK + k0 + a_koff) * 2);
            uint32_t bf[8][2];
#pragma unroll
            for (int nj = 0; nj < 4; nj++) {
                uint32_t r0, r1, r2, r3;
                ldsm4(r0, r1, r2, r3,
                      bBase + (uint32_t)((b_row + nj * 16) * LDK + k0 + b_koff) * 2);
                bf[2 * nj][0] = r0; bf[2 * nj][1] = r1;
                bf[2 * nj + 1][0] = r2; bf[2 * nj + 1][1] = r3;
            }
#pragma unroll
            for (int mi = 0; mi < 4; mi++)
#pragma unroll
                for (int ni = 0; ni < 8; ni++) {
                    asm volatile(
                        "mma.sync.aligned.m16n8k16.row.col.f32.f16.f16.f32 "
                        "{%0,%1,%2,%3}, {%4,%5,%6,%7}, {%8,%9}, {%0,%1,%2,%3};\n"
                        : "+f"(acc[mi][ni][0]), "+f"(acc[mi][ni][1]),
                          "+f"(acc[mi][ni][2]), "+f"(acc[mi][ni][3])
                        : "r"(af[mi][0]), "r"(af[mi][1]), "r"(af[mi][2]), "r"(af[mi][3]),
                          "r"(bf[ni][0]), "r"(bf[ni][1]));
                }
        }
    }

    // ---------------- epilogue ----------------
    float sig = 1.f;
    if (EPI == EPI_FUSED) sig = 1.f / (1.f + expf(-gatep[0]));

#pragma unroll
    for (int mi = 0; mi < 4; mi++) {
#pragma unroll
        for (int ni = 0; ni < 8; ni++) {
            const int col = n0 + wn * 64 + ni * 8 + 2 * c;
            const float b0 = bias[col], b1 = bias[col + 1];
#pragma unroll
            for (int half_ = 0; half_ < 2; half_++) {
                const int row = m0 + wm * 64 + mi * 16 + g + half_ * 8;
                const size_t oi = (size_t)row * N + col;
                float v0 = acc[mi][ni][half_ * 2 + 0] + b0;
                float v1 = acc[mi][ni][half_ * 2 + 1] + b1;
                if (EPI == EPI_F32) {
                    *(float2*)((float*)outp + oi) = make_float2(v0, v1);
                } else if (EPI == EPI_HALF) {
                    *(__half2*)((__half*)outp + oi) = __floats2half2_rn(v0, v1);
                } else if (EPI == EPI_FUSED) {
                    float2 a2 = *(const float2*)(aux + oi);
                    *(float2*)((float*)outp + oi) =
                        make_float2(a2.x + sig * v0, a2.y + sig * v1);
                } else if (EPI == EPI_GELU_H) {
                    *(__half2*)((__half*)outp + oi) =
                        __floats2half2_rn(gelu_f(v0), gelu_f(v1));
                } else { // EPI_ADDOUT
                    float2 a2 = *(const float2*)(aux + oi);
                    *(float2*)((float*)outp + oi) = make_float2(a2.x + v0, a2.y + v1);
                }
            }
        }
    }
}

// ================= weight transpose 64x64: Wt[n][k] = (half)W[k][n] =================
__global__ __launch_bounds__(256)
void transpose_w(const float* __restrict__ in, __half* __restrict__ out,
                 int rows, int cols)
{
    __shared__ float t[64][65];
    const int bx = blockIdx.x * 64;   // input col tile
    const int by = blockIdx.y * 64;   // input row tile
#pragma unroll
    for (int i = threadIdx.x; i < 1024; i += 256) {
        int r = i >> 4, c4 = (i & 15) * 4;
        float4 v = *(const float4*)&in[(size_t)(by + r) * cols + bx + c4];
        t[r][c4] = v.x; t[r][c4 + 1] = v.y; t[r][c4 + 2] = v.z; t[r][c4 + 3] = v.w;
    }
    __syncthreads();
#pragma unroll
    for (int i = threadIdx.x; i < 1024; i += 256) {
        int cc = i >> 4, r4 = (i & 15) * 4;
        __half2 h0 = __floats2half2_rn(t[r4][cc],     t[r4 + 1][cc]);
        __half2 h1 = __floats2half2_rn(t[r4 + 2][cc], t[r4 + 3][cc]);
        uint2 pk = make_uint2(*(uint32_t*)&h0, *(uint32_t*)&h1);
        *(uint2*)&out[(size_t)(bx + cc) * rows + by + r4] = pk;
    }
}

// ================= bias concat =================
__global__ void concat_bias(const float* __restrict__ a, const float* __restrict__ b,
                            float* __restrict__ o)
{
    int i = blockIdx.x * blockDim.x + threadIdx.x;
    o[i] = (i < 1024) ? a[i] : b[i - 1024];
}

// ================= phys MLP stage 1 (32 rows per block, pw1 reused) =================
__global__ __launch_bounds__(256)
void phys_mlp1(const float* __restrict__ phys, const float* __restrict__ pw1,
               const float* __restrict__ pb1, __half* __restrict__ out)
{
    __shared__ float p[32][PHYSD + 1];
    const int b0 = blockIdx.x * 32;
    const int tid = threadIdx.x;
    for (int i = tid; i < 32 * PHYSD; i += 256) {
        int r = i / PHYSD, k = i % PHYSD;
        p[r][k] = phys[(size_t)(b0 + r) * PHYSD + k];
    }
    __syncthreads();

    for (int n = tid; n < DN; n += 256) {
        float w[PHYSD];
#pragma unroll
        for (int k = 0; k < PHYSD; k++) w[k] = pw1[(size_t)k * DN + n];
        const float bb = pb1[n];
#pragma unroll 4
        for (int r = 0; r < 32; r++) {
            float s = bb;
#pragma unroll
            for (int k = 0; k < PHYSD; k++) s = fmaf(p[r][k], w[k], s);
            out[(size_t)(b0 + r) * DN + n] = __float2half_rn(gelu_f(s));
        }
    }
}

// ================= LayerNorm (D=1024), templated input, fp16 out =================
template <typename IT>
__global__ __launch_bounds__(256)
void ln1024(const IT* __restrict__ x, const float* __restrict__ gg,
            const float* __restrict__ bb, __half* __restrict__ out)
{
    __shared__ float red1[8], red2[8];
    const int row = blockIdx.x;
    const int tid = threadIdx.x;
    const int lane = tid & 31, wid = tid >> 5;

    float4 v;
    if (sizeof(IT) == 4) {
        v = *(const float4*)((const float*)x + (size_t)row * DMODEL + tid * 4);
    } else {
        uint2 pk = *(const uint2*)((const __half*)x + (size_t)row * DMODEL + tid * 4);
        float2 f0 = __half22float2(*(__half2*)&pk.x);
        float2 f1 = __half22float2(*(__half2*)&pk.y);
        v = make_float4(f0.x, f0.y, f1.x, f1.y);
    }
    float s1 = v.x + v.y + v.z + v.w;
    float s2 = v.x * v.x + v.y * v.y + v.z * v.z + v.w * v.w;
#pragma unroll
    for (int o = 16; o > 0; o >>= 1) {
        s1 += __shfl_down_sync(0xFFFFFFFFu, s1, o);
        s2 += __shfl_down_sync(0xFFFFFFFFu, s2, o);
    }
    if (lane == 0) { red1[wid] = s1; red2[wid] = s2; }
    __syncthreads();
    if (tid == 0) {
        float a = 0.f, b2 = 0.f;
#pragma unroll
        for (int i = 0; i < 8; i++) { a += red1[i]; b2 += red2[i]; }
        red1[0] = a; red2[0] = b2;
    }
    __syncthreads();
    const float mu  = red1[0] * (1.f / DMODEL);
    const float var = red2[0] * (1.f / DMODEL) - mu * mu;
    const float rs  = rsqrtf(var + LN_EPS);

    float4 gv = *(const float4*)(gg + tid * 4);
    float4 bv = *(const float4*)(bb + tid * 4);
    __half2 o0 = __floats2half2_rn((v.x - mu) * rs * gv.x + bv.x,
                                   (v.y - mu) * rs * gv.y + bv.y);
    __half2 o1 = __floats2half2_rn((v.z - mu) * rs * gv.z + bv.z,
                                   (v.w - mu) * rs * gv.w + bv.w);
    uint2 pk = make_uint2(*(uint32_t*)&o0, *(uint32_t*)&o1);
    *(uint2*)(out + (size_t)row * DMODEL + tid * 4) = pk;
}

// ================= attention: warp per (b, head), packed kv =================
__device__ __forceinline__ float dot8h(uint4 a, uint4 b) {
    const __half2* pa = (const __half2*)&a;
    const __half2* pb = (const __half2*)&b;
    float s = 0.f;
#pragma unroll
    for (int i = 0; i < 4; i++) {
        float2 fa = __half22float2(pa[i]);
        float2 fb = __half22float2(pb[i]);
        s = fmaf(fa.x, fb.x, s);
        s = fmaf(fa.y, fb.y, s);
    }
    return s;
}

__global__ __launch_bounds__(256)
void attn_kernel(const __half* __restrict__ q, const __half* __restrict__ kv,
                 __half* __restrict__ ctx)
{
    int warp = (blockIdx.x * 256 + threadIdx.x) >> 5;
    int lane = threadIdx.x & 31;
    int b = warp >> 2, h = warp & 3;

    size_t qoff = (size_t)b * DMODEL + h * DHEAD;
    uint4 qv = *(const uint4*)(q + qoff + lane * 8);

    float s[NTOK];
#pragma unroll
    for (int t = 0; t < NTOK; t++) {
        size_t koff = (size_t)(b * NTOK + t) * 2048 + h * DHEAD;
        uint4 kvec = *(const uint4*)(kv + koff + lane * 8);
        float d = dot8h(qv, kvec);
#pragma unroll
        for (int o = 16; o > 0; o >>= 1) d += __shfl_xor_sync(0xFFFFFFFFu, d, o);
        s[t] = d * (1.f / 16.f);   // 1/sqrt(256)
    }
    float m = fmaxf(fmaxf(s[0], s[1]), fmaxf(s[2], s[3]));
    float e[NTOK], sum = 0.f;
#pragma unroll
    for (int t = 0; t < NTOK; t++) { e[t] = expf(s[t] - m); sum += e[t]; }
    float inv = 1.f / sum;

    float cacc[8];
#pragma unroll
    for (int i = 0; i < 8; i++) cacc[i] = 0.f;
#pragma unroll
    for (int t = 0; t < NTOK; t++) {
        float a = e[t] * inv;
        size_t voff = (size_t)(b * NTOK + t) * 2048 + 1024 + h * DHEAD;
        uint4 vv = *(const uint4*)(kv + voff + lane * 8);
        const __half2* pv = (const __half2*)&vv;
#pragma unroll
        for (int i = 0; i < 4; i++) {
            float2 f = __half22float2(pv[i]);
            cacc[2 * i]     = fmaf(a, f.x, cacc[2 * i]);
            cacc[2 * i + 1] = fmaf(a, f.y, cacc[2 * i + 1]);
        }
    }
    uint4 ov;
    __half2* po = (__half2*)&ov;
#pragma unroll
    for (int i = 0; i < 4; i++)
        po[i] = __floats2half2_rn(cacc[2 * i], cacc[2 * i + 1]);
    *(uint4*)(ctx + qoff + lane * 8) = ov;
}

// ================= host launcher =================
extern "C" void kernel_launch(void* const* d_in, const int* in_sizes, int n_in,
                              void* d_out, int out_size)
{
    const float* embedding = (const float*)d_in[0];
    const float* physics   = (const float*)d_in[1];
    const float* pw1   = (const float*)d_in[2];
    const float* pb1   = (const float*)d_in[3];
    const float* pw2   = (const float*)d_in[4];
    const float* pb2   = (const float*)d_in[5];
    const float* lnq_g = (const float*)d_in[6];
    const float* lnq_b = (const float*)d_in[7];
    const float* lnkv_g = (const float*)d_in[8];
    const float* lnkv_b = (const float*)d_in[9];
    const float* wq = (const float*)d_in[10];
    const float* bq = (const float*)d_in[11];
    const float* wk = (const float*)d_in[12];
    const float* bk = (const float*)d_in[13];
    const float* wv = (const float*)d_in[14];
    const float* bv = (const float*)d_in[15];
    const float* wo = (const float*)d_in[16];
    const float* bo = (const float*)d_in[17];
    const float* ffn_g = (const float*)d_in[18];
    const float* ffn_b = (const float*)d_in[19];
    const float* fw1 = (const float*)d_in[20];
    const float* fb1 = (const float*)d_in[21];
    const float* fw2 = (const float*)d_in[22];
    const float* fb2 = (const float*)d_in[23];
    const float* gate = (const float*)d_in[24];
    float* out = (float*)d_out;

    __half *p_h, *p_physkv, *p_kvln, *p_qln, *p_qproj, *p_kv, *p_ctx, *p_fusedln, *p_ffh;
    __half *wt_pw2, *wt_q, *wt_kv, *wt_o, *wt_f1, *wt_f2;
    float  *p_fused, *p_bkv;
    cudaGetSymbolAddress((void**)&p_h, g_h);
    cudaGetSymbolAddress((void**)&p_physkv, g_physkv);
    cudaGetSymbolAddress((void**)&p_kvln, g_kvln);
    cudaGetSymbolAddress((void**)&p_qln, g_qln);
    cudaGetSymbolAddress((void**)&p_qproj, g_qproj);
    cudaGetSymbolAddress((void**)&p_kv, g_kv);
    cudaGetSymbolAddress((void**)&p_ctx, g_ctx);
    cudaGetSymbolAddress((void**)&p_fused, g_fused);
    cudaGetSymbolAddress((void**)&p_fusedln, g_fusedln);
    cudaGetSymbolAddress((void**)&p_ffh, g_ffh);
    cudaGetSymbolAddress((void**)&wt_pw2, g_wt_pw2);
    cudaGetSymbolAddress((void**)&wt_q, g_wt_q);
    cudaGetSymbolAddress((void**)&wt_kv, g_wt_kv);
    cudaGetSymbolAddress((void**)&wt_o, g_wt_o);
    cudaGetSymbolAddress((void**)&wt_f1, g_wt_f1);
    cudaGetSymbolAddress((void**)&wt_f2, g_wt_f2);
    cudaGetSymbolAddress((void**)&p_bkv, g_b_kv);

    cudaFuncSetAttribute(gemm_h<EPI_HALF>,   cudaFuncAttributeMaxDynamicSharedMemorySize, SMEM_TOT);
    cudaFuncSetAttribute(gemm_h<EPI_FUSED>,  cudaFuncAttributeMaxDynamicSharedMemorySize, SMEM_TOT);
    cudaFuncSetAttribute(gemm_h<EPI_GELU_H>, cudaFuncAttributeMaxDynamicSharedMemorySize, SMEM_TOT);
    cudaFuncSetAttribute(gemm_h<EPI_ADDOUT>, cudaFuncAttributeMaxDynamicSharedMemorySize, SMEM_TOT);

    // ---- streams / events (graph-capture fork/join) ----
    cudaStream_t s2;
    cudaStreamCreateWithFlags(&s2, cudaStreamNonBlocking);
    cudaEvent_t evF, evPW2, evKV, evW, evG1, evG2, evLN1, evLN2,
                evKV1, evKV2, evA1, evA2, evFU1, evFU2, evL1, evL2;
    cudaEvent_t* evs[] = {&evF, &evPW2, &evKV, &evW, &evG1, &evG2, &evLN1, &evLN2,
                          &evKV1, &evKV2, &evA1, &evA2, &evFU1, &evFU2, &evL1, &evL2};
    for (auto e : evs) cudaEventCreateWithFlags(e, cudaEventDisableTiming);

    // fork
    cudaEventRecord(evF, 0);
    cudaStreamWaitEvent(s2, evF, 0);

    // ---- side stream: weight prep + q branch ----
    transpose_w<<<dim3(DN / 64, DN / 64), 256, 0, s2>>>(pw2, wt_pw2, DN, DN);
    cudaEventRecord(evPW2, s2);
    transpose_w<<<dim3(DMODEL / 64, DMODEL / 64), 256, 0, s2>>>(wk, wt_kv, DMODEL, DMODEL);
    transpose_w<<<dim3(DMODEL / 64, DMODEL / 64), 256, 0, s2>>>(
        wv, wt_kv + (size_t)DMODEL * DMODEL, DMODEL, DMODEL);
    concat_bias<<<2, 1024, 0, s2>>>(bk, bv, p_bkv);
    cudaEventRecord(evKV, s2);
    transpose_w<<<dim3(DMODEL / 64, DMODEL / 64), 256, 0, s2>>>(wq, wt_q, DMODEL, DMODEL);
    ln1024<float><<<BATCH, 256, 0, s2>>>(embedding, lnq_g, lnq_b, p_qln);
    gemm_h<EPI_HALF><<<dim3(DMODEL / 256, BATCH / 128), 256, SMEM_TOT, s2>>>(
        p_qln, wt_q, bq, p_qproj, nullptr, nullptr, DMODEL, DMODEL);
    transpose_w<<<dim3(DMODEL / 64, DMODEL / 64), 256, 0, s2>>>(wo, wt_o, DMODEL, DMODEL);
    transpose_w<<<dim3(2048 / 64, DMODEL / 64), 256, 0, s2>>>(fw1, wt_f1, DMODEL, 2048);
    transpose_w<<<dim3(DMODEL / 64, 2048 / 64), 256, 0, s2>>>(fw2, wt_f2, 2048, DMODEL);
    cudaEventRecord(evW, s2);    // covers qproj + all remaining transposes

    // ---- main: phys stage 1 (parallel with pw2 transpose on s2) ----
    phys_mlp1<<<BATCH / 32, 256>>>(physics, pw1, pb1, p_h);

    // ---- BIG GEMM in half-M, lnkv of half1 overlaps half2 ----
    cudaStreamWaitEvent(0, evPW2, 0);
    gemm_h<EPI_HALF><<<dim3(DN / 256, HB / 128), 256, SMEM_TOT>>>(
        p_h, wt_pw2, pb2, p_physkv, nullptr, nullptr, DN, DN);
    cudaEventRecord(evG1, 0);
    gemm_h<EPI_HALF><<<dim3(DN / 256, HB / 128), 256, SMEM_TOT>>>(
        p_h + (size_t)HB * DN, wt_pw2, pb2, p_physkv + (size_t)HB * DN,
        nullptr, nullptr, DN, DN);
    cudaEventRecord(evG2, 0);

    cudaStreamWaitEvent(s2, evG1, 0);
    ln1024<__half><<<HB * NTOK, 256, 0, s2>>>(p_physkv, lnkv_g, lnkv_b, p_kvln);
    cudaEventRecord(evLN1, s2);
    cudaStreamWaitEvent(s2, evG2, 0);
    ln1024<__half><<<HB * NTOK, 256, 0, s2>>>(
        p_physkv + (size_t)HB * DN, lnkv_g, lnkv_b, p_kvln + (size_t)HB * DN);
    cudaEventRecord(evLN2, s2);

    // ---- kv GEMM in half-M, attn of half1 overlaps half2 ----
    cudaStreamWaitEvent(0, evLN1, 0);
    cudaStreamWaitEvent(0, evKV, 0);
    gemm_h<EPI_HALF><<<dim3(2048 / 256, (HB * NTOK) / 128), 256, SMEM_TOT>>>(
        p_kvln, wt_kv, p_bkv, p_kv, nullptr, nullptr, 2048, DMODEL);
    cudaEventRecord(evKV1, 0);
    cudaStreamWaitEvent(0, evLN2, 0);
    gemm_h<EPI_HALF><<<dim3(2048 / 256, (HB * NTOK) / 128), 256, SMEM_TOT>>>(
        p_kvln + (size_t)HB * NTOK * DMODEL, wt_kv, p_bkv,
        p_kv + (size_t)HB * NTOK * 2048, nullptr, nullptr, 2048, DMODEL);
    cudaEventRecord(evKV2, 0);

    cudaStreamWaitEvent(s2, evKV1, 0);   // qproj already ordered on s2
    attn_kernel<<<(HB * NHEAD) / 8, 256, 0, s2>>>(p_qproj, p_kv, p_ctx);
    cudaEventRecord(evA1, s2);
    cudaStreamWaitEvent(s2, evKV2, 0);
    attn_kernel<<<(HB * NHEAD) / 8, 256, 0, s2>>>(
        p_qproj + (size_t)HB * DMODEL, p_kv + (size_t)HB * NTOK * 2048,
        p_ctx + (size_t)HB * DMODEL);
    cudaEventRecord(evA2, s2);

    // ---- fused GEMM in half-M, ln_fused of half1 overlaps half2 ----
    cudaStreamWaitEvent(0, evA1, 0);
    cudaStreamWaitEvent(0, evW, 0);
    gemm_h<EPI_FUSED><<<dim3(DMODEL / 256, HB / 128), 256, SMEM_TOT>>>(
        p_ctx, wt_o, bo, p_fused, embedding, gate, DMODEL, DMODEL);
    cudaEventRecord(evFU1, 0);
    cudaStreamWaitEvent(0, evA2, 0);
    gemm_h<EPI_FUSED><<<dim3(DMODEL / 256, HB / 128), 256, SMEM_TOT>>>(
        p_ctx + (size_t)HB * DMODEL, wt_o, bo, p_fused + (size_t)HB * DMODEL,
        embedding + (size_t)HB * DMODEL, gate, DMODEL, DMODEL);
    cudaEventRecord(evFU2, 0);

    cudaStreamWaitEvent(s2, evFU1, 0);
    ln1024<float><<<HB, 256, 0, s2>>>(p_fused, ffn_g, ffn_b, p_fusedln);
    cudaEventRecord(evL1, s2);
    cudaStreamWaitEvent(s2, evFU2, 0);
    ln1024<float><<<HB, 256, 0, s2>>>(
        p_fused + (size_t)HB * DMODEL, ffn_g, ffn_b, p_fusedln + (size_t)HB * DMODEL);
    cudaEventRecord(evL2, s2);

    // ---- FFN (unsplit: splitting gelu GEMM costs a wave) ----
    cudaStreamWaitEvent(0, evL1, 0);
    cudaStreamWaitEvent(0, evL2, 0);
    gemm_h<EPI_GELU_H><<<dim3(2048 / 256, BATCH / 128), 256, SMEM_TOT>>>(
        p_fusedln, wt_f1, fb1, p_ffh, nullptr, nullptr, 2048, DMODEL);
    gemm_h<EPI_ADDOUT><<<dim3(DMODEL / 256, BATCH / 128), 256, SMEM_TOT>>>(
        p_ffh, wt_f2, fb2, out, p_fused, nullptr, DMODEL, 2048);
}

// round 16
// speedup vs baseline: 1.4311x; 1.0461x over previous
#include <cuda_runtime.h>
#include <cuda_fp16.h>
#include <cstdint>
#include <cstddef>

// ---------------- problem constants ----------------
#define BATCH   16384
#define HB      8192                 // BATCH/2 (half-M pipelining)
#define DMODEL  1024
#define PHYSD   11
#define NTOK    4
#define NHEAD   4
#define DHEAD   256
#define DN      4096
#define LN_EPS  1e-5f

// ---------------- device scratch (allocation-free rule) ----------------
__device__ __half g_h      [(size_t)BATCH * DN];
__device__ __half g_physkv [(size_t)BATCH * DN];
__device__ __half g_kvln   [(size_t)BATCH * DN];
__device__ __half g_qln    [(size_t)BATCH * DMODEL];
__device__ __half g_qproj  [(size_t)BATCH * DMODEL];
__device__ __half g_kv     [(size_t)BATCH * NTOK * 2048];   // [k(1024)|v(1024)] per token
__device__ __half g_ctx    [(size_t)BATCH * DMODEL];
__device__ float  g_fused  [(size_t)BATCH * DMODEL];
__device__ __half g_fusedln[(size_t)BATCH * DMODEL];
__device__ __half g_ffh    [(size_t)BATCH * 2048];
// transposed weights [N][K] fp16
__device__ __half g_wt_pw2 [(size_t)DN * DN];
__device__ __half g_wt_q   [(size_t)DMODEL * DMODEL];
__device__ __half g_wt_kv  [(size_t)2048 * DMODEL];
__device__ __half g_wt_o   [(size_t)DMODEL * DMODEL];
__device__ __half g_wt_f1  [(size_t)2048 * DMODEL];
__device__ __half g_wt_f2  [(size_t)DMODEL * 2048];
__device__ float  g_b_kv   [2048];

// ---------------- helpers ----------------
__device__ __forceinline__ float gelu_f(float x) {
    float x3 = x * x * x;
    float t  = tanhf(0.79788456080286535588f * (x + 0.044715f * x3));
    return 0.5f * x * (1.0f + t);
}
__device__ __forceinline__ void cpa16(uint32_t sdst, const void* gsrc) {
    asm volatile("cp.async.cg.shared.global [%0], [%1], 16;\n" :: "r"(sdst), "l"(gsrc));
}
__device__ __forceinline__ void ldsm4(uint32_t& r0, uint32_t& r1, uint32_t& r2, uint32_t& r3,
                                      uint32_t addr) {
    asm volatile("ldmatrix.sync.aligned.m8n8.x4.shared.b16 {%0,%1,%2,%3}, [%4];"
                 : "=r"(r0), "=r"(r1), "=r"(r2), "=r"(r3) : "r"(addr));
}

// ================= fp16 GEMM: out[M,N] = A[M,K] @ Wt[N,K]^T + bias =================
// BM=128 BN=256 BK=128, 256 threads = 8 warps (2M x 4N), warp tile 64x64.
// fp32-accum m16n8k16, ldmatrix, 2-stage double buffer with prefetch distance 1:
//   wait(fill kt) -> barrier -> issue fill(kt+1) into other stage -> compute kt.
// One barrier per 128-K tile; fill of kt+1 overlaps the 8192-cyc compute of kt.
enum { EPI_F32 = 0, EPI_HALF = 1, EPI_FUSED = 2, EPI_GELU_H = 3, EPI_ADDOUT = 4 };

#define LDK        136                        // halves per smem row (128 + 8 pad)
#define A_BYTES    (128 * LDK * 2)            // 34816
#define B_BYTES    (256 * LDK * 2)            // 69632
#define STAGE_B    (A_BYTES + B_BYTES)        // 104448
#define NSTAGE     2
#define SMEM_TOT   (STAGE_B * NSTAGE)         // 208896

template <int EPI>
__global__ __launch_bounds__(256, 1)
void gemm_h(const __half* __restrict__ A, const __half* __restrict__ Wt,
            const float* __restrict__ bias, void* __restrict__ outp,
            const float* __restrict__ aux, const float* __restrict__ gatep,
            int N, int K)
{
    extern __shared__ char smem[];
    const uint32_t sb = (uint32_t)__cvta_generic_to_shared(smem);

    const int tid  = threadIdx.x;
    const int lane = tid & 31;
    const int wid  = tid >> 5;
    const int wm   = wid >> 2;          // 0..1
    const int wn   = wid & 3;           // 0..3
    const int g    = lane >> 2;         // 0..7
    const int c    = lane & 3;          // 0..3
    const int m0   = blockIdx.y * 128;
    const int n0   = blockIdx.x * 256;

    const int a_row  = wm * 64 + (lane & 15);                      // + mi*16
    const int a_koff = (lane >> 4) << 3;                           // 0 or 8
    const int b_row  = wn * 64 + ((lane >> 4) << 3) + (lane & 7);  // + nj*16
    const int b_koff = lane & 8;                                   // 0 or 8

    float acc[4][8][4];
#pragma unroll
    for (int mi = 0; mi < 4; mi++)
#pragma unroll
        for (int ni = 0; ni < 8; ni++)
#pragma unroll
            for (int e = 0; e < 4; e++) acc[mi][ni][e] = 0.f;

    const int nt = K >> 7;              // 128-K tiles

    auto fill = [&](int s, int kt) {
        const uint32_t a0 = sb + (uint32_t)s * STAGE_B;
        const uint32_t b0 = a0 + A_BYTES;
        const __half* Ag = A  + (size_t)m0 * K + kt * 128;
        const __half* Bg = Wt + (size_t)n0 * K + kt * 128;
#pragma unroll
        for (int i = 0; i < 8; i++) {
            int idx = tid + 256 * i;          // 0..2047  (128 rows x 16 chunks)
            int r = idx >> 4, c8 = idx & 15;
            cpa16(a0 + (uint32_t)(r * LDK + c8 * 8) * 2, Ag + (size_t)r * K + c8 * 8);
        }
#pragma unroll
        for (int i = 0; i < 16; i++) {
            int idx = tid + 256 * i;          // 0..4095  (256 rows x 16 chunks)
            int r = idx >> 4, c8 = idx & 15;
            cpa16(b0 + (uint32_t)(r * LDK + c8 * 8) * 2, Bg + (size_t)r * K + c8 * 8);
        }
        asm volatile("cp.async.commit_group;" ::: "memory");
    };

    fill(0, 0);

    for (int kt = 0; kt < nt; kt++) {
        // drain the (single) in-flight fill of tile kt
        asm volatile("cp.async.wait_group 0;" ::: "memory");
        __syncthreads();   // all warps done reading the other stage (iter kt-1)

        // prefetch next tile into the other stage; overlaps this tile's compute
        if (kt + 1 < nt) fill((kt + 1) & 1, kt + 1);

        const int s = kt & 1;
        const uint32_t aBase = sb + (uint32_t)s * STAGE_B;
        const uint32_t bBase = aBase + A_BYTES;

#pragma unroll
        for (int ks = 0; ks < 8; ks++) {
            const int k0 = ks * 16;
            uint32_t af[4][4];
#pragma unroll
            for (int mi = 0; mi < 4; mi++)
                ldsm4(af[mi][0], af[mi][1], af[mi][2], af[mi][3],
                      aBase + (uint32_t)((a_row + mi * 16) * LDK + k0 + a_koff) * 2);
            uint32_t bf[8][2];
#pragma unroll
            for (int nj = 0; nj < 4; nj++) {
                uint32_t r0, r1, r2, r3;
                ldsm4(r0, r1, r2, r3,
                      bBase + (uint32_t)((b_row + nj * 16) * LDK + k0 + b_koff) * 2);
                bf[2 * nj][0] = r0; bf[2 * nj][1] = r1;
                bf[2 * nj + 1][0] = r2; bf[2 * nj + 1][1] = r3;
            }
#pragma unroll
            for (int mi = 0; mi < 4; mi++)
#pragma unroll
                for (int ni = 0; ni < 8; ni++) {
                    asm volatile(
                        "mma.sync.aligned.m16n8k16.row.col.f32.f16.f16.f32 "
                        "{%0,%1,%2,%3}, {%4,%5,%6,%7}, {%8,%9}, {%0,%1,%2,%3};\n"
                        : "+f"(acc[mi][ni][0]), "+f"(acc[mi][ni][1]),
                          "+f"(acc[mi][ni][2]), "+f"(acc[mi][ni][3])
                        : "r"(af[mi][0]), "r"(af[mi][1]), "r"(af[mi][2]), "r"(af[mi][3]),
                          "r"(bf[ni][0]), "r"(bf[ni][1]));
                }
        }
    }

    // ---------------- epilogue ----------------
    float sig = 1.f;
    if (EPI == EPI_FUSED) sig = 1.f / (1.f + expf(-gatep[0]));

#pragma unroll
    for (int mi = 0; mi < 4; mi++) {
#pragma unroll
        for (int ni = 0; ni < 8; ni++) {
            const int col = n0 + wn * 64 + ni * 8 + 2 * c;
            const float b0 = bias[col], b1 = bias[col + 1];
#pragma unroll
            for (int half_ = 0; half_ < 2; half_++) {
                const int row = m0 + wm * 64 + mi * 16 + g + half_ * 8;
                const size_t oi = (size_t)row * N + col;
                float v0 = acc[mi][ni][half_ * 2 + 0] + b0;
                float v1 = acc[mi][ni][half_ * 2 + 1] + b1;
                if (EPI == EPI_F32) {
                    *(float2*)((float*)outp + oi) = make_float2(v0, v1);
                } else if (EPI == EPI_HALF) {
                    *(__half2*)((__half*)outp + oi) = __floats2half2_rn(v0, v1);
                } else if (EPI == EPI_FUSED) {
                    float2 a2 = *(const float2*)(aux + oi);
                    *(float2*)((float*)outp + oi) =
                        make_float2(a2.x + sig * v0, a2.y + sig * v1);
                } else if (EPI == EPI_GELU_H) {
                    *(__half2*)((__half*)outp + oi) =
                        __floats2half2_rn(gelu_f(v0), gelu_f(v1));
                } else { // EPI_ADDOUT
                    float2 a2 = *(const float2*)(aux + oi);
                    *(float2*)((float*)outp + oi) = make_float2(a2.x + v0, a2.y + v1);
                }
            }
        }
    }
}

// ================= weight transpose 64x64: Wt[n][k] = (half)W[k][n] =================
__global__ __launch_bounds__(256)
void transpose_w(const float* __restrict__ in, __half* __restrict__ out,
                 int rows, int cols)
{
    __shared__ float t[64][65];
    const int bx = blockIdx.x * 64;   // input col tile
    const int by = blockIdx.y * 64;   // input row tile
#pragma unroll
    for (int i = threadIdx.x; i < 1024; i += 256) {
        int r = i >> 4, c4 = (i & 15) * 4;
        float4 v = *(const float4*)&in[(size_t)(by + r) * cols + bx + c4];
        t[r][c4] = v.x; t[r][c4 + 1] = v.y; t[r][c4 + 2] = v.z; t[r][c4 + 3] = v.w;
    }
    __syncthreads();
#pragma unroll
    for (int i = threadIdx.x; i < 1024; i += 256) {
        int cc = i >> 4, r4 = (i & 15) * 4;
        __half2 h0 = __floats2half2_rn(t[r4][cc],     t[r4 + 1][cc]);
        __half2 h1 = __floats2half2_rn(t[r4 + 2][cc], t[r4 + 3][cc]);
        uint2 pk = make_uint2(*(uint32_t*)&h0, *(uint32_t*)&h1);
        *(uint2*)&out[(size_t)(bx + cc) * rows + by + r4] = pk;
    }
}

// ================= bias concat =================
__global__ void concat_bias(const float* __restrict__ a, const float* __restrict__ b,
                            float* __restrict__ o)
{
    int i = blockIdx.x * blockDim.x + threadIdx.x;
    o[i] = (i < 1024) ? a[i] : b[i - 1024];
}

// ================= phys MLP stage 1 (32 rows per block, pw1 reused) =================
__global__ __launch_bounds__(256)
void phys_mlp1(const float* __restrict__ phys, const float* __restrict__ pw1,
               const float* __restrict__ pb1, __half* __restrict__ out)
{
    __shared__ float p[32][PHYSD + 1];
    const int b0 = blockIdx.x * 32;
    const int tid = threadIdx.x;
    for (int i = tid; i < 32 * PHYSD; i += 256) {
        int r = i / PHYSD, k = i % PHYSD;
        p[r][k] = phys[(size_t)(b0 + r) * PHYSD + k];
    }
    __syncthreads();

    for (int n = tid; n < DN; n += 256) {
        float w[PHYSD];
#pragma unroll
        for (int k = 0; k < PHYSD; k++) w[k] = pw1[(size_t)k * DN + n];
        const float bb = pb1[n];
#pragma unroll 4
        for (int r = 0; r < 32; r++) {
            float s = bb;
#pragma unroll
            for (int k = 0; k < PHYSD; k++) s = fmaf(p[r][k], w[k], s);
            out[(size_t)(b0 + r) * DN + n] = __float2half_rn(gelu_f(s));
        }
    }
}

// ================= LayerNorm (D=1024), templated input, fp16 out =================
template <typename IT>
__global__ __launch_bounds__(256)
void ln1024(const IT* __restrict__ x, const float* __restrict__ gg,
            const float* __restrict__ bb, __half* __restrict__ out)
{
    __shared__ float red1[8], red2[8];
    const int row = blockIdx.x;
    const int tid = threadIdx.x;
    const int lane = tid & 31, wid = tid >> 5;

    float4 v;
    if (sizeof(IT) == 4) {
        v = *(const float4*)((const float*)x + (size_t)row * DMODEL + tid * 4);
    } else {
        uint2 pk = *(const uint2*)((const __half*)x + (size_t)row * DMODEL + tid * 4);
        float2 f0 = __half22float2(*(__half2*)&pk.x);
        float2 f1 = __half22float2(*(__half2*)&pk.y);
        v = make_float4(f0.x, f0.y, f1.x, f1.y);
    }
    float s1 = v.x + v.y + v.z + v.w;
    float s2 = v.x * v.x + v.y * v.y + v.z * v.z + v.w * v.w;
#pragma unroll
    for (int o = 16; o > 0; o >>= 1) {
        s1 += __shfl_down_sync(0xFFFFFFFFu, s1, o);
        s2 += __shfl_down_sync(0xFFFFFFFFu, s2, o);
    }
    if (lane == 0) { red1[wid] = s1; red2[wid] = s2; }
    __syncthreads();
    if (tid == 0) {
        float a = 0.f, b2 = 0.f;
#pragma unroll
        for (int i = 0; i < 8; i++) { a += red1[i]; b2 += red2[i]; }
        red1[0] = a; red2[0] = b2;
    }
    __syncthreads();
    const float mu  = red1[0] * (1.f / DMODEL);
    const float var = red2[0] * (1.f / DMODEL) - mu * mu;
    const float rs  = rsqrtf(var + LN_EPS);

    float4 gv = *(const float4*)(gg + tid * 4);
    float4 bv = *(const float4*)(bb + tid * 4);
    __half2 o0 = __floats2half2_rn((v.x - mu) * rs * gv.x + bv.x,
                                   (v.y - mu) * rs * gv.y + bv.y);
    __half2 o1 = __floats2half2_rn((v.z - mu) * rs * gv.z + bv.z,
                                   (v.w - mu) * rs * gv.w + bv.w);
    uint2 pk = make_uint2(*(uint32_t*)&o0, *(uint32_t*)&o1);
    *(uint2*)(out + (size_t)row * DMODEL + tid * 4) = pk;
}

// ================= attention: warp per (b, head), packed kv =================
__device__ __forceinline__ float dot8h(uint4 a, uint4 b) {
    const __half2* pa = (const __half2*)&a;
    const __half2* pb = (const __half2*)&b;
    float s = 0.f;
#pragma unroll
    for (int i = 0; i < 4; i++) {
        float2 fa = __half22float2(pa[i]);
        float2 fb = __half22float2(pb[i]);
        s = fmaf(fa.x, fb.x, s);
        s = fmaf(fa.y, fb.y, s);
    }
    return s;
}

__global__ __launch_bounds__(256)
void attn_kernel(const __half* __restrict__ q, const __half* __restrict__ kv,
                 __half* __restrict__ ctx)
{
    int warp = (blockIdx.x * 256 + threadIdx.x) >> 5;
    int lane = threadIdx.x & 31;
    int b = warp >> 2, h = warp & 3;

    size_t qoff = (size_t)b * DMODEL + h * DHEAD;
    uint4 qv = *(const uint4*)(q + qoff + lane * 8);

    float s[NTOK];
#pragma unroll
    for (int t = 0; t < NTOK; t++) {
        size_t koff = (size_t)(b * NTOK + t) * 2048 + h * DHEAD;
        uint4 kvec = *(const uint4*)(kv + koff + lane * 8);
        float d = dot8h(qv, kvec);
#pragma unroll
        for (int o = 16; o > 0; o >>= 1) d += __shfl_xor_sync(0xFFFFFFFFu, d, o);
        s[t] = d * (1.f / 16.f);   // 1/sqrt(256)
    }
    float m = fmaxf(fmaxf(s[0], s[1]), fmaxf(s[2], s[3]));
    float e[NTOK], sum = 0.f;
#pragma unroll
    for (int t = 0; t < NTOK; t++) { e[t] = expf(s[t] - m); sum += e[t]; }
    float inv = 1.f / sum;

    float cacc[8];
#pragma unroll
    for (int i = 0; i < 8; i++) cacc[i] = 0.f;
#pragma unroll
    for (int t = 0; t < NTOK; t++) {
        float a = e[t] * inv;
        size_t voff = (size_t)(b * NTOK + t) * 2048 + 1024 + h * DHEAD;
        uint4 vv = *(const uint4*)(kv + voff + lane * 8);
        const __half2* pv = (const __half2*)&vv;
#pragma unroll
        for (int i = 0; i < 4; i++) {
            float2 f = __half22float2(pv[i]);
            cacc[2 * i]     = fmaf(a, f.x, cacc[2 * i]);
            cacc[2 * i + 1] = fmaf(a, f.y, cacc[2 * i + 1]);
        }
    }
    uint4 ov;
    __half2* po = (__half2*)&ov;
#pragma unroll
    for (int i = 0; i < 4; i++)
        po[i] = __floats2half2_rn(cacc[2 * i], cacc[2 * i + 1]);
    *(uint4*)(ctx + qoff + lane * 8) = ov;
}

// ================= host launcher =================
extern "C" void kernel_launch(void* const* d_in, const int* in_sizes, int n_in,
                              void* d_out, int out_size)
{
    const float* embedding = (const float*)d_in[0];
    const float* physics   = (const float*)d_in[1];
    const float* pw1   = (const float*)d_in[2];
    const float* pb1   = (const float*)d_in[3];
    const float* pw2   = (const float*)d_in[4];
    const float* pb2   = (const float*)d_in[5];
    const float* lnq_g = (const float*)d_in[6];
    const float* lnq_b = (const float*)d_in[7];
    const float* lnkv_g = (const float*)d_in[8];
    const float* lnkv_b = (const float*)d_in[9];
    const float* wq = (const float*)d_in[10];
    const float* bq = (const float*)d_in[11];
    const float* wk = (const float*)d_in[12];
    const float* bk = (const float*)d_in[13];
    const float* wv = (const float*)d_in[14];
    const float* bv = (const float*)d_in[15];
    const float* wo = (const float*)d_in[16];
    const float* bo = (const float*)d_in[17];
    const float* ffn_g = (const float*)d_in[18];
    const float* ffn_b = (const float*)d_in[19];
    const float* fw1 = (const float*)d_in[20];
    const float* fb1 = (const float*)d_in[21];
    const float* fw2 = (const float*)d_in[22];
    const float* fb2 = (const float*)d_in[23];
    const float* gate = (const float*)d_in[24];
    float* out = (float*)d_out;

    __half *p_h, *p_physkv, *p_kvln, *p_qln, *p_qproj, *p_kv, *p_ctx, *p_fusedln, *p_ffh;
    __half *wt_pw2, *wt_q, *wt_kv, *wt_o, *wt_f1, *wt_f2;
    float  *p_fused, *p_bkv;
    cudaGetSymbolAddress((void**)&p_h, g_h);
    cudaGetSymbolAddress((void**)&p_physkv, g_physkv);
    cudaGetSymbolAddress((void**)&p_kvln, g_kvln);
    cudaGetSymbolAddress((void**)&p_qln, g_qln);
    cudaGetSymbolAddress((void**)&p_qproj, g_qproj);
    cudaGetSymbolAddress((void**)&p_kv, g_kv);
    cudaGetSymbolAddress((void**)&p_ctx, g_ctx);
    cudaGetSymbolAddress((void**)&p_fused, g_fused);
    cudaGetSymbolAddress((void**)&p_fusedln, g_fusedln);
    cudaGetSymbolAddress((void**)&p_ffh, g_ffh);
    cudaGetSymbolAddress((void**)&wt_pw2, g_wt_pw2);
    cudaGetSymbolAddress((void**)&wt_q, g_wt_q);
    cudaGetSymbolAddress((void**)&wt_kv, g_wt_kv);
    cudaGetSymbolAddress((void**)&wt_o, g_wt_o);
    cudaGetSymbolAddress((void**)&wt_f1, g_wt_f1);
    cudaGetSymbolAddress((void**)&wt_f2, g_wt_f2);
    cudaGetSymbolAddress((void**)&p_bkv, g_b_kv);

    cudaFuncSetAttribute(gemm_h<EPI_HALF>,   cudaFuncAttributeMaxDynamicSharedMemorySize, SMEM_TOT);
    cudaFuncSetAttribute(gemm_h<EPI_FUSED>,  cudaFuncAttributeMaxDynamicSharedMemorySize, SMEM_TOT);
    cudaFuncSetAttribute(gemm_h<EPI_GELU_H>, cudaFuncAttributeMaxDynamicSharedMemorySize, SMEM_TOT);
    cudaFuncSetAttribute(gemm_h<EPI_ADDOUT>, cudaFuncAttributeMaxDynamicSharedMemorySize, SMEM_TOT);

    // ---- streams / events (graph-capture fork/join) ----
    cudaStream_t s2;
    cudaStreamCreateWithFlags(&s2, cudaStreamNonBlocking);
    cudaEvent_t evF, evPW2, evKV, evW, evG1, evG2, evLN1, evLN2,
                evKV1, evKV2, evA1, evA2, evFU1, evFU2, evL1, evL2;
    cudaEvent_t* evs[] = {&evF, &evPW2, &evKV, &evW, &evG1, &evG2, &evLN1, &evLN2,
                          &evKV1, &evKV2, &evA1, &evA2, &evFU1, &evFU2, &evL1, &evL2};
    for (auto e : evs) cudaEventCreateWithFlags(e, cudaEventDisableTiming);

    // fork
    cudaEventRecord(evF, 0);
    cudaStreamWaitEvent(s2, evF, 0);

    // ---- side stream: weight prep + q branch ----
    transpose_w<<<dim3(DN / 64, DN / 64), 256, 0, s2>>>(pw2, wt_pw2, DN, DN);
    cudaEventRecord(evPW2, s2);
    transpose_w<<<dim3(DMODEL / 64, DMODEL / 64), 256, 0, s2>>>(wk, wt_kv, DMODEL, DMODEL);
    transpose_w<<<dim3(DMODEL / 64, DMODEL / 64), 256, 0, s2>>>(
        wv, wt_kv + (size_t)DMODEL * DMODEL, DMODEL, DMODEL);
    concat_bias<<<2, 1024, 0, s2>>>(bk, bv, p_bkv);
    cudaEventRecord(evKV, s2);
    transpose_w<<<dim3(DMODEL / 64, DMODEL / 64), 256, 0, s2>>>(wq, wt_q, DMODEL, DMODEL);
    ln1024<float><<<BATCH, 256, 0, s2>>>(embedding, lnq_g, lnq_b, p_qln);
    gemm_h<EPI_HALF><<<dim3(DMODEL / 256, BATCH / 128), 256, SMEM_TOT, s2>>>(
        p_qln, wt_q, bq, p_qproj, nullptr, nullptr, DMODEL, DMODEL);
    transpose_w<<<dim3(DMODEL / 64, DMODEL / 64), 256, 0, s2>>>(wo, wt_o, DMODEL, DMODEL);
    transpose_w<<<dim3(2048 / 64, DMODEL / 64), 256, 0, s2>>>(fw1, wt_f1, DMODEL, 2048);
    transpose_w<<<dim3(DMODEL / 64, 2048 / 64), 256, 0, s2>>>(fw2, wt_f2, 2048, DMODEL);
    cudaEventRecord(evW, s2);    // covers qproj + all remaining transposes

    // ---- main: phys stage 1 (parallel with pw2 transpose on s2) ----
    phys_mlp1<<<BATCH / 32, 256>>>(physics, pw1, pb1, p_h);

    // ---- BIG GEMM in half-M, lnkv of half1 overlaps half2 ----
    cudaStreamWaitEvent(0, evPW2, 0);
    gemm_h<EPI_HALF><<<dim3(DN / 256, HB / 128), 256, SMEM_TOT>>>(
        p_h, wt_pw2, pb2, p_physkv, nullptr, nullptr, DN, DN);
    cudaEventRecord(evG1, 0);
    gemm_h<EPI_HALF><<<dim3(DN / 256, HB / 128), 256, SMEM_TOT>>>(
        p_h + (size_t)HB * DN, wt_pw2, pb2, p_physkv + (size_t)HB * DN,
        nullptr, nullptr, DN, DN);
    cudaEventRecord(evG2, 0);

    cudaStreamWaitEvent(s2, evG1, 0);
    ln1024<__half><<<HB * NTOK, 256, 0, s2>>>(p_physkv, lnkv_g, lnkv_b, p_kvln);
    cudaEventRecord(evLN1, s2);
    cudaStreamWaitEvent(s2, evG2, 0);
    ln1024<__half><<<HB * NTOK, 256, 0, s2>>>(
        p_physkv + (size_t)HB * DN, lnkv_g, lnkv_b, p_kvln + (size_t)HB * DN);
    cudaEventRecord(evLN2, s2);

    // ---- kv GEMM in half-M, attn of half1 overlaps half2 ----
    cudaStreamWaitEvent(0, evLN1, 0);
    cudaStreamWaitEvent(0, evKV, 0);
    gemm_h<EPI_HALF><<<dim3(2048 / 256, (HB * NTOK) / 128), 256, SMEM_TOT>>>(
        p_kvln, wt_kv, p_bkv, p_kv, nullptr, nullptr, 2048, DMODEL);
    cudaEventRecord(evKV1, 0);
    cudaStreamWaitEvent(0, evLN2, 0);
    gemm_h<EPI_HALF><<<dim3(2048 / 256, (HB * NTOK) / 128), 256, SMEM_TOT>>>(
        p_kvln + (size_t)HB * NTOK * DMODEL, wt_kv, p_bkv,
        p_kv + (size_t)HB * NTOK * 2048, nullptr, nullptr, 2048, DMODEL);
    cudaEventRecord(evKV2, 0);

    cudaStreamWaitEvent(s2, evKV1, 0);   // qproj already ordered on s2
    attn_kernel<<<(HB * NHEAD) / 8, 256, 0, s2>>>(p_qproj, p_kv, p_ctx);
    cudaEventRecord(evA1, s2);
    cudaStreamWaitEvent(s2, evKV2, 0);
    attn_kernel<<<(HB * NHEAD) / 8, 256, 0, s2>>>(
        p_qproj + (size_t)HB * DMODEL, p_kv + (size_t)HB * NTOK * 2048,
        p_ctx + (size_t)HB * DMODEL);
    cudaEventRecord(evA2, s2);

    // ---- fused GEMM in half-M, ln_fused of half1 overlaps half2 ----
    cudaStreamWaitEvent(0, evA1, 0);
    cudaStreamWaitEvent(0, evW, 0);
    gemm_h<EPI_FUSED><<<dim3(DMODEL / 256, HB / 128), 256, SMEM_TOT>>>(
        p_ctx, wt_o, bo, p_fused, embedding, gate, DMODEL, DMODEL);
    cudaEventRecord(evFU1, 0);
    cudaStreamWaitEvent(0, evA2, 0);
    gemm_h<EPI_FUSED><<<dim3(DMODEL / 256, HB / 128), 256, SMEM_TOT>>>(
        p_ctx + (size_t)HB * DMODEL, wt_o, bo, p_fused + (size_t)HB * DMODEL,
        embedding + (size_t)HB * DMODEL, gate, DMODEL, DMODEL);
    cudaEventRecord(evFU2, 0);

    cudaStreamWaitEvent(s2, evFU1, 0);
    ln1024<float><<<HB, 256, 0, s2>>>(p_fused, ffn_g, ffn_b, p_fusedln);
    cudaEventRecord(evL1, s2);
    cudaStreamWaitEvent(s2, evFU2, 0);
    ln1024<float><<<HB, 256, 0, s2>>>(
        p_fused + (size_t)HB * DMODEL, ffn_g, ffn_b, p_fusedln + (size_t)HB * DMODEL);
    cudaEventRecord(evL2, s2);

    // ---- FFN (unsplit: splitting gelu GEMM costs a wave) ----
    cudaStreamWaitEvent(0, evL1, 0);
    cudaStreamWaitEvent(0, evL2, 0);
    gemm_h<EPI_GELU_H><<<dim3(2048 / 256, BATCH / 128), 256, SMEM_TOT>>>(
        p_fusedln, wt_f1, fb1, p_ffh, nullptr, nullptr, 2048, DMODEL);
    gemm_h<EPI_ADDOUT><<<dim3(DMODEL / 256, BATCH / 128), 256, SMEM_TOT>>>(
        p_ffh, wt_f2, fb2, out, p_fused, nullptr, DMODEL, 2048);
}